// round 13
// baseline (speedup 1.0000x reference)
#include <cuda_runtime.h>
#include <math.h>

#define NS 1024

__device__ float g_h1p[NS*32*36*16];
__device__ float g_h2p[NS*64*12*4];
__device__ float g_h3p[NS*128*4*2];
__device__ float g_w2t[4*192*64];
__device__ float g_w3t[16*96*128];
__device__ float g_e [NS*128];
__device__ float g_q [NS*128];
__device__ float g_k [NS*128];
__device__ float g_v [NS*128];
__device__ float g_ao[NS*128];
__device__ float g_o2[NS*128];
__device__ float g_ea[NS*128];
__device__ float g_sq[NS];
__device__ float g_css[128];
__device__ float g_css2[128];
__device__ unsigned int g_dmax;

__device__ __forceinline__ float selu_f(float x) {
    const float a = 1.6732632423543772f, sc = 1.0507009873554805f;
    return x > 0.f ? sc * x : sc * a * (expf(x) - 1.f);
}

__device__ __forceinline__ float2 ffma2(float2 a, float2 b, float2 c) {
    unsigned long long ua = *(unsigned long long*)&a;
    unsigned long long ub = *(unsigned long long*)&b;
    unsigned long long uc = *(unsigned long long*)&c;
    unsigned long long ud;
    asm("fma.rn.f32x2 %0, %1, %2, %3;" : "=l"(ud) : "l"(ua), "l"(ub), "l"(uc));
    return *(float2*)&ud;
}

__device__ __forceinline__ unsigned tf32c(float x) {
    unsigned u; asm("cvt.rna.tf32.f32 %0, %1;" : "=r"(u) : "f"(x)); return u;
}
__device__ __forceinline__ float tf32f(float x) {
    return __uint_as_float(tf32c(x));
}
__device__ __forceinline__ void mma_tf32(float* d, const unsigned* a, const unsigned* b) {
    asm volatile("mma.sync.aligned.m16n8k8.row.col.f32.tf32.tf32.f32 "
        "{%0,%1,%2,%3}, {%4,%5,%6,%7}, {%8,%9}, {%0,%1,%2,%3};"
        : "+f"(d[0]), "+f"(d[1]), "+f"(d[2]), "+f"(d[3])
        : "r"(a[0]), "r"(a[1]), "r"(a[2]), "r"(a[3]), "r"(b[0]), "r"(b[1]));
}

__global__ void k_zero() {
    int t = threadIdx.x;
    if (t < 128) { g_css[t] = 0.f; g_css2[t] = 0.f; }
    if (t == 255) g_dmax = 0u;
}

__global__ void __launch_bounds__(256) k_prep(const float* __restrict__ w2,
        const float* __restrict__ w3) {
    int i = blockIdx.x*256 + threadIdx.x;
    if (i < 49152)  g_w2t[i] = tf32f(w2[(i&63)*768 + (i>>6)]);
    if (i < 196608) g_w3t[i] = tf32f(w3[(i&127)*1536 + (i>>7)]);
}

// ===== conv1: 1 block/frame, 32 ch (FFMA2). Stores tf32-converted output =====
__global__ void __launch_bounds__(256) k_conv1(const float* __restrict__ x,
        const float* __restrict__ w, const float* __restrict__ bias,
        const float* __restrict__ gg, const float* __restrict__ gb) {
    __shared__ __align__(16) float pad[77*68];
    int s = blockIdx.x, tid = threadIdx.x, lane = tid & 31;
    const float* xs = x + s*4608;
    for (int i = tid; i < 77*68; i += 256) {
        int r = i/68, cc = i - r*68;
        int ih = r-2, iw = cc-1;
        pad[i] = (ih>=0 && ih<72 && iw>=0 && iw<64) ? xs[ih*64+iw] : 0.f;
    }
    __syncthreads();
    for (int cc4 = 0; cc4 < 4; cc4++) {
        int ch = cc4*8 + (tid>>5);
        float2 w2[24];
        #pragma unroll
        for (int k2 = 0; k2 < 24; k2++) { float wv = w[ch*24+k2]; w2[k2] = make_float2(wv, wv); }
        float bi = bias[ch];
        float pm[18], pn[18], sum = 0.f, sq = 0.f;
        for (int wi = 0; wi < 18; wi++) {
            int wdw = wi*32 + lane;
            int ph = wdw>>4, pw = wdw&15;
            float2 acc[2][2];
            #pragma unroll
            for (int r = 0; r < 2; r++)
                #pragma unroll
                for (int cp = 0; cp < 2; cp++) acc[r][cp] = make_float2(bi, bi);
            #pragma unroll
            for (int ir = 0; ir < 7; ir++) {
                const float* pr = &pad[(2*ph+ir)*68 + 4*pw];
                float4 va = *(const float4*)pr;
                float4 vb = *(const float4*)(pr + 4);
                float v[7] = {va.x, va.y, va.z, va.w, vb.x, vb.y, vb.z};
                #pragma unroll
                for (int r = 0; r < 2; r++) {
                    int kh = ir - r;
                    if (kh >= 0 && kh < 6) {
                        #pragma unroll
                        for (int kw = 0; kw < 4; kw++) {
                            float2 wv = w2[kh*4+kw];
                            #pragma unroll
                            for (int cp = 0; cp < 2; cp++)
                                acc[r][cp] = ffma2(make_float2(v[2*cp+kw], v[2*cp+kw+1]), wv, acc[r][cp]);
                        }
                    }
                }
            }
            float mx = -1e30f, mn = 1e30f;
            #pragma unroll
            for (int r = 0; r < 2; r++)
                #pragma unroll
                for (int cp = 0; cp < 2; cp++) {
                    float u0 = selu_f(acc[r][cp].x), u1 = selu_f(acc[r][cp].y);
                    sum += u0+u1; sq += u0*u0+u1*u1;
                    mx = fmaxf(mx, fmaxf(u0,u1)); mn = fminf(mn, fminf(u0,u1));
                }
            pm[wi] = mx; pn[wi] = mn;
        }
        #pragma unroll
        for (int o = 16; o; o >>= 1) {
            sum += __shfl_xor_sync(0xffffffffu, sum, o);
            sq  += __shfl_xor_sync(0xffffffffu, sq , o);
        }
        float mean = sum*(1.f/4608.f);
        float var  = sq*(1.f/4608.f) - mean*mean;
        float sc = gg[ch]*rsqrtf(var+1e-5f);
        float sh = gb[ch] - mean*sc;
        for (int wi = 0; wi < 18; wi++) {
            int wdw = wi*32 + lane;
            int ph = wdw>>4, pw = wdw&15;
            float val = sc>0.f ? pm[wi]*sc+sh : pn[wi]*sc+sh;
            g_h1p[((s*32+ch)*36+ph)*16+pw] = tf32f(val);
        }
    }
}

// ===== conv2: TF32 mma, 384 thr / 12 warps (2 blocks/SM), fused GN+pool =====
#define C2_SMEM (32*577*4)
__global__ void __launch_bounds__(384, 2) k_conv2mma(const float* __restrict__ bias,
        const float* __restrict__ gg, const float* __restrict__ gb) {
    extern __shared__ float dsm[];
    float* ws   = dsm;          // 192 x 33 (tf32 bits)
    float* padc = dsm + 6336;   // 8 x 779 (tf32 bits)
    float* cv   = dsm;          // aliased after compute: 32 x 577
    int s = blockIdx.x, ocb = 32*blockIdx.y;
    int tid = threadIdx.x, wrp = tid>>5, t = tid&31;
    int m = wrp & 1, ng = wrp >> 1;       // ng 0..5, 96 n each
    float cfr[12][4];
    #pragma unroll
    for (int j = 0; j < 12; j++) { cfr[j][0]=cfr[j][1]=cfr[j][2]=cfr[j][3]=0.f; }
    int off[12];
    #pragma unroll
    for (int j = 0; j < 12; j++) {
        int n = ng*96 + j*8 + (t>>2);
        off[j] = (n>>4)*19 + (n&15);
    }
    for (int ck = 0; ck < 4; ck++) {
        __syncthreads();
        #pragma unroll
        for (int u = 0; u < 16; u++) {
            int i = tid + u*384;
            ws[(i>>5)*33 + (i&31)] = g_w2t[ck*12288 + (i>>5)*64 + ocb + (i&31)];
        }
        for (int i = tid; i < 6232; i += 384) {
            int icl = i/779, rem = i - icl*779;
            int row = rem/19, col = rem - row*19;
            int ih = row - 2, iw = col - 1;
            padc[i] = (ih>=0 && ih<36 && iw>=0 && iw<16)
                    ? g_h1p[((s*32 + ck*8 + icl)*36 + ih)*16 + iw] : 0.f;
        }
        __syncthreads();
        #pragma unroll 1
        for (int sl = 0; sl < 24; sl++) {
            int icl = sl/3, t8 = (sl - icl*3)*8;
            int kk = icl*24 + t8 + (t&3);
            unsigned A[4];
            A[0] = __float_as_uint(ws[kk*33 + m*16 + (t>>2)]);
            A[1] = __float_as_uint(ws[kk*33 + m*16 + (t>>2) + 8]);
            A[2] = __float_as_uint(ws[(kk+4)*33 + m*16 + (t>>2)]);
            A[3] = __float_as_uint(ws[(kk+4)*33 + m*16 + (t>>2) + 8]);
            const float* pb = padc + icl*779 + (t8>>2)*19 + (t&3);
            #pragma unroll
            for (int j = 0; j < 12; j++) {
                unsigned B[2];
                B[0] = __float_as_uint(pb[off[j]]);
                B[1] = __float_as_uint(pb[off[j] + 19]);
                mma_tf32(cfr[j], A, B);
            }
        }
    }
    __syncthreads();
    int ocl = m*16 + (t>>2);
    float b0v = bias[ocb+ocl], b8v = bias[ocb+ocl+8];
    #pragma unroll
    for (int j = 0; j < 12; j++) {
        int n0 = ng*96 + j*8 + (t&3)*2;
        cv[ocl*577 + n0]     = selu_f(cfr[j][0] + b0v);
        cv[ocl*577 + n0 + 1] = selu_f(cfr[j][1] + b0v);
        cv[(ocl+8)*577 + n0]     = selu_f(cfr[j][2] + b8v);
        cv[(ocl+8)*577 + n0 + 1] = selu_f(cfr[j][3] + b8v);
    }
    __syncthreads();
    if (tid < 256) {
        int g = tid>>4, e = tid&15;
        float sm = 0.f, sq = 0.f;
        #pragma unroll
        for (int cl = 0; cl < 2; cl++)
            for (int i = e; i < 576; i += 16) {
                float v = cv[(2*g+cl)*577 + i];
                sm += v; sq += v*v;
            }
        #pragma unroll
        for (int o = 8; o; o >>= 1) {
            sm += __shfl_xor_sync(0xffffffffu, sm, o);
            sq += __shfl_xor_sync(0xffffffffu, sq, o);
        }
        float mean = sm*(1.f/1152.f);
        float var  = sq*(1.f/1152.f) - mean*mean;
        float inv  = rsqrtf(var + 1e-5f);
        #pragma unroll
        for (int ii = 0; ii < 6; ii++) {
            int u = e + 16*ii;
            int cl = u/48, rem = u - cl*48;
            int ph = rem>>2, pw = rem&3;
            float scv = gg[ocb+2*g+cl]*inv;
            float shv = gb[ocb+2*g+cl] - mean*scv;
            float mx = -1e30f;
            #pragma unroll
            for (int r = 0; r < 3; r++)
                #pragma unroll
                for (int c = 0; c < 4; c++)
                    mx = fmaxf(mx, cv[(2*g+cl)*577 + (3*ph+r)*16 + 4*pw+c]*scv + shv);
            g_h2p[((s*64 + ocb + 2*g + cl)*12 + ph)*4 + pw] = tf32f(mx);
        }
    }
}

// ===== conv3: TF32 mma, 4 frames/block, grid 256, 512 thr, fused GN+pool =====
#define C3_SMEM (96*132*4)
__global__ void __launch_bounds__(512) k_conv3mma4(const float* __restrict__ bias,
        const float* __restrict__ gg, const float* __restrict__ gb) {
    extern __shared__ float ws[];
    __shared__ float pad[4*476];
    float* cv = ws;
    int s4 = blockIdx.x*4, tid = threadIdx.x, wrp = tid>>5, t = tid&31;
    int m = wrp & 7, ng = wrp >> 3;
    float cfr[12][4];
    #pragma unroll
    for (int j = 0; j < 12; j++) { cfr[j][0]=cfr[j][1]=cfr[j][2]=cfr[j][3]=0.f; }
    int off[12];
    #pragma unroll
    for (int j = 0; j < 12; j++) {
        int n = ng*96 + j*8 + (t>>2);
        int f = (ng*96 + j*8)/48;
        int np = n - 48*f;
        off[j] = f*476 + (np>>2)*7 + (np&3);
    }
    for (int ck = 0; ck < 16; ck++) {
        __syncthreads();
        #pragma unroll
        for (int u = 0; u < 6; u++) {
            int i = (tid + u*512)*4;
            float4 wv4 = *(const float4*)&g_w3t[ck*12288 + i];
            *(float4*)&ws[(i>>7)*132 + (i&127)] = wv4;
        }
        for (int i = tid; i < 1904; i += 512) {
            int f = i/476, rem = i - f*476;
            int icl = rem/119, rem2 = rem - icl*119;
            int rr = rem2/7, cc = rem2 - rr*7;
            int ih = rr-2, iw = cc-1;
            pad[i] = (ih>=0 && ih<12 && iw>=0 && iw<4)
                   ? g_h2p[(((s4+f)*64 + ck*4 + icl)*12 + ih)*4 + iw] : 0.f;
        }
        __syncthreads();
        #pragma unroll 1
        for (int sl = 0; sl < 12; sl++) {
            int icl = sl/3, t8 = (sl - icl*3)*8;
            int kk = icl*24 + t8 + (t&3);
            unsigned A[4];
            A[0] = __float_as_uint(ws[kk*132 + m*16 + (t>>2)]);
            A[1] = __float_as_uint(ws[kk*132 + m*16 + (t>>2) + 8]);
            A[2] = __float_as_uint(ws[(kk+4)*132 + m*16 + (t>>2)]);
            A[3] = __float_as_uint(ws[(kk+4)*132 + m*16 + (t>>2) + 8]);
            const float* pb = pad + icl*119 + (t8>>2)*7 + (t&3);
            #pragma unroll
            for (int j = 0; j < 12; j++) {
                unsigned B[2];
                B[0] = __float_as_uint(pb[off[j]]);
                B[1] = __float_as_uint(pb[off[j] + 7]);
                mma_tf32(cfr[j], A, B);
            }
        }
    }
    int oc0 = m*16 + (t>>2);
    float b0v = bias[oc0], b8v = bias[oc0+8];
    for (int f = 0; f < 4; f++) {
        __syncthreads();
        #pragma unroll
        for (int j = 0; j < 12; j++) {
            int fj = ng*2 + j/6;
            if (fj == f) {
                int np = (j - (j/6)*6)*8 + (t&3)*2;
                cv[oc0*49 + np]     = selu_f(cfr[j][0] + b0v);
                cv[oc0*49 + np + 1] = selu_f(cfr[j][1] + b0v);
                cv[(oc0+8)*49 + np]     = selu_f(cfr[j][2] + b8v);
                cv[(oc0+8)*49 + np + 1] = selu_f(cfr[j][3] + b8v);
            }
        }
        __syncthreads();
        int g = tid>>4, e = tid&15;
        float sm = 0.f, sq = 0.f;
        #pragma unroll
        for (int cl = 0; cl < 4; cl++)
            for (int i = e; i < 48; i += 16) {
                float v = cv[(4*g+cl)*49 + i];
                sm += v; sq += v*v;
            }
        #pragma unroll
        for (int o = 8; o; o >>= 1) {
            sm += __shfl_xor_sync(0xffffffffu, sm, o);
            sq += __shfl_xor_sync(0xffffffffu, sq, o);
        }
        float mean = sm*(1.f/192.f);
        float var  = sq*(1.f/192.f) - mean*mean;
        float inv  = rsqrtf(var + 1e-5f);
        #pragma unroll
        for (int ii = 0; ii < 2; ii++) {
            int u = e + 16*ii;
            int cl = u>>3, rem = u&7;
            int ph = rem>>1, pw = rem&1;
            float scv = gg[4*g+cl]*inv;
            float shv = gb[4*g+cl] - mean*scv;
            float mx = -1e30f;
            #pragma unroll
            for (int r = 0; r < 3; r++)
                #pragma unroll
                for (int c = 0; c < 2; c++)
                    mx = fmaxf(mx, cv[(4*g+cl)*49 + (3*ph+r)*4 + 2*pw+c]*scv + shv);
            g_h3p[(((s4+f)*128 + 4*g + cl)*4 + ph)*2 + pw] = mx;
        }
    }
}

// ===== fc =====
__global__ void __launch_bounds__(256) k_fc(const float* __restrict__ w,
        const float* __restrict__ bias) {
    __shared__ float xs[8*65];
    __shared__ float wt[64*129];
    __shared__ float sred[8][4];
    int r0 = blockIdx.x*8, tid = threadIdx.x;
    int c = tid&127, rg = tid>>7, wrp = tid>>5, ln = tid&31;
    float acc[4];
    float b0 = bias[c];
    #pragma unroll
    for (int rr = 0; rr < 4; rr++) acc[rr] = b0;
    for (int k0 = 0; k0 < 1024; k0 += 64) {
        __syncthreads();
        for (int i = tid; i < 512; i += 256) {
            int r = i>>6, kk = i&63;
            xs[r*65+kk] = g_h3p[(r0+r)*1024 + k0 + kk];
        }
        for (int i = tid; i < 8192; i += 256) {
            int j = i>>6, kk = i&63;
            wt[kk*129+j] = w[j*1024 + k0 + kk];
        }
        __syncthreads();
        for (int kk = 0; kk < 64; kk++) {
            float wv = wt[kk*129+c];
            #pragma unroll
            for (int rr = 0; rr < 4; rr++) acc[rr] += xs[(rg*4+rr)*65+kk]*wv;
        }
    }
    float v[4];
    #pragma unroll
    for (int rr = 0; rr < 4; rr++) v[rr] = selu_f(acc[rr]);
    #pragma unroll
    for (int rr = 0; rr < 4; rr++) {
        float ss = v[rr]*v[rr];
        #pragma unroll
        for (int o = 16; o; o >>= 1) ss += __shfl_xor_sync(0xffffffffu, ss, o);
        if (ln == 0) sred[wrp][rr] = ss;
    }
    __syncthreads();
    #pragma unroll
    for (int rr = 0; rr < 4; rr++) {
        float t = sred[rg*4+0][rr] + sred[rg*4+1][rr] + sred[rg*4+2][rr] + sred[rg*4+3][rr];
        float n = fmaxf(sqrtf(t), 1e-12f);
        g_e[(r0+rg*4+rr)*128 + c] = v[rr]/n;
    }
}

// ===== qkv =====
__global__ void __launch_bounds__(256) k_qkv(const float* __restrict__ wq,
        const float* __restrict__ bq, const float* __restrict__ wk,
        const float* __restrict__ bk, const float* __restrict__ wv,
        const float* __restrict__ bv) {
    __shared__ float es[8*132];
    __shared__ float wt[64*129];
    int r0 = blockIdx.x*8, tid = threadIdx.x;
    int c = tid&127, rg = tid>>7;
    for (int i = tid; i < 1024; i += 256) {
        int r = i>>7, d = i&127;
        es[r*132+d] = g_e[(r0+r)*128 + d];
    }
    const float* W[3] = {wq, wk, wv};
    const float* B[3] = {bq, bk, bv};
    float* O[3] = {g_q, g_k, g_v};
    for (int m = 0; m < 3; m++) {
        float acc[4];
        float b0 = B[m][c];
        #pragma unroll
        for (int rr = 0; rr < 4; rr++) acc[rr] = b0;
        for (int k0 = 0; k0 < 128; k0 += 64) {
            __syncthreads();
            for (int i = tid; i < 8192; i += 256) {
                int j = i>>6, kk = i&63;
                wt[kk*129+j] = W[m][j*128 + k0 + kk];
            }
            __syncthreads();
            for (int kk = 0; kk < 64; kk++) {
                float wvv = wt[kk*129+c];
                #pragma unroll
                for (int rr = 0; rr < 4; rr++) acc[rr] += es[(rg*4+rr)*132 + k0 + kk]*wvv;
            }
        }
        #pragma unroll
        for (int rr = 0; rr < 4; rr++) {
            int sr = r0 + rg*4 + rr;
            float u = selu_f(acc[rr]);
            if (m == 1) {
                float f = expf((float)(c & ~1) * (-9.210340371976184f/128.f));
                float ang = (float)sr * f;
                u += (c & 1) ? cosf(ang) : sinf(ang);
            }
            O[m][sr*128 + c] = u;
        }
    }
}

// ===== attn =====
__global__ void __launch_bounds__(256) k_attn() {
    __shared__ __align__(16) float q8[8*132];
    __shared__ __align__(16) float p[8*1024];
    __shared__ float rinv[8];
    int r0 = blockIdx.x*8, tid = threadIdx.x;
    for (int i = tid; i < 1024; i += 256) {
        int r = i>>7, d = i&127;
        q8[r*132+d] = g_q[(r0+r)*128 + d];
    }
    __syncthreads();
    const float scale = 0.08838834764831845f;
    for (int t = tid; t < 1024; t += 256) {
        float2 a2[8];
        #pragma unroll
        for (int r = 0; r < 8; r++) a2[r] = make_float2(0.f, 0.f);
        const float4* kr = (const float4*)(g_k + t*128);
        #pragma unroll 4
        for (int d4 = 0; d4 < 32; d4++) {
            float4 kv = kr[d4];
            float2 klo = make_float2(kv.x, kv.y), khi = make_float2(kv.z, kv.w);
            #pragma unroll
            for (int r = 0; r < 8; r++) {
                float4 qv = *(const float4*)&q8[r*132 + d4*4];
                a2[r] = ffma2(make_float2(qv.x, qv.y), klo, a2[r]);
                a2[r] = ffma2(make_float2(qv.z, qv.w), khi, a2[r]);
            }
        }
        #pragma unroll
        for (int r = 0; r < 8; r++) p[r*1024+t] = (a2[r].x + a2[r].y)*scale;
    }
    __syncthreads();
    int wrp = tid>>5, ln = tid&31;
    {
        int r = wrp;
        float mxv = -1e30f;
        for (int t = ln; t < 1024; t += 32) mxv = fmaxf(mxv, p[r*1024+t]);
        #pragma unroll
        for (int o = 16; o; o >>= 1) mxv = fmaxf(mxv, __shfl_xor_sync(0xffffffffu, mxv, o));
        float sm = 0.f;
        for (int t = ln; t < 1024; t += 32) {
            float e = expf(p[r*1024+t] - mxv);
            p[r*1024+t] = e;
            sm += e;
        }
        #pragma unroll
        for (int o = 16; o; o >>= 1) sm += __shfl_xor_sync(0xffffffffu, sm, o);
        if (ln == 0) rinv[r] = 1.f/sm;
    }
    __syncthreads();
    int c2 = tid&63, hf = tid>>6;
    float2 acc2[8];
    #pragma unroll
    for (int r = 0; r < 8; r++) acc2[r] = make_float2(0.f, 0.f);
    for (int t = hf*256; t < hf*256+256; t++) {
        float2 vv = *(const float2*)&g_v[t*128 + 2*c2];
        #pragma unroll
        for (int r = 0; r < 8; r++) {
            float pv = p[r*1024+t];
            acc2[r] = ffma2(make_float2(pv, pv), vv, acc2[r]);
        }
    }
    __syncthreads();
    float2* pbuf = (float2*)p;
    if (hf) {
        #pragma unroll
        for (int r = 0; r < 8; r++) pbuf[(hf-1)*512 + r*64 + c2] = acc2[r];
    }
    __syncthreads();
    if (hf == 0) {
        #pragma unroll
        for (int r = 0; r < 8; r++) {
            float2 sv = acc2[r];
            #pragma unroll
            for (int q = 0; q < 3; q++) {
                float2 o = pbuf[q*512 + r*64 + c2];
                sv.x += o.x; sv.y += o.y;
            }
            g_ao[(r0+r)*128 + 2*c2]     = sv.x*rinv[r];
            g_ao[(r0+r)*128 + 2*c2 + 1] = sv.y*rinv[r];
        }
    }
}

__global__ void __launch_bounds__(256) k_cs1() {
    __shared__ float red[128];
    int s0 = blockIdx.x*16, tid = threadIdx.x;
    int c = tid&127, sy = tid>>7;
    float ss = 0.f;
    for (int s = sy; s < 16; s += 2) { float v = g_ao[(s0+s)*128+c]; ss += v*v; }
    if (sy) red[c] = ss;
    __syncthreads();
    if (!sy) atomicAdd(&g_css[c], ss + red[c]);
}

__global__ void __launch_bounds__(256) k_cs2() {
    __shared__ float red[128];
    int s0 = blockIdx.x*16, tid = threadIdx.x;
    int c = tid&127, sy = tid>>7;
    float inv1 = 1.f/fmaxf(sqrtf(g_css[c]), 1e-12f);
    float ss = 0.f;
    for (int s = sy; s < 16; s += 2) {
        float v = g_ao[(s0+s)*128+c]*inv1 + g_e[(s0+s)*128+c];
        g_o2[(s0+s)*128+c] = v;
        ss += v*v;
    }
    if (sy) red[c] = ss;
    __syncthreads();
    if (!sy) atomicAdd(&g_css2[c], ss + red[c]);
}

__global__ void __launch_bounds__(128) k_cs3r() {
    __shared__ float red[4];
    int s = blockIdx.x, d = threadIdx.x;
    int wrp = d>>5, ln = d&31;
    float inv2 = 1.f/fmaxf(sqrtf(g_css2[d]), 1e-12f);
    float v = g_o2[s*128+d]*inv2;
    g_ea[s*128+d] = v;
    float ss = v*v;
    #pragma unroll
    for (int o = 16; o; o >>= 1) ss += __shfl_xor_sync(0xffffffffu, ss, o);
    if (ln == 0) red[wrp] = ss;
    __syncthreads();
    if (d == 0) g_sq[s] = red[0]+red[1]+red[2]+red[3];
}

__global__ void k_gram(float* __restrict__ dout) {
    __shared__ float ea_i[32][129];
    __shared__ float ea_j[32][129];
    __shared__ float sqi[32], sqj[32];
    __shared__ float rmax[8];
    int i0 = blockIdx.y*32, j0 = blockIdx.x*32;
    int tid = threadIdx.x;
    for (int idx = tid; idx < 4096; idx += 256) {
        int r = idx>>7, d = idx&127;
        ea_i[r][d] = g_ea[(i0+r)*128+d];
        ea_j[r][d] = g_ea[(j0+r)*128+d];
    }
    if (tid < 32) { sqi[tid] = g_sq[i0+tid]; sqj[tid] = g_sq[j0+tid]; }
    __syncthreads();
    int tx = tid&15, ty = tid>>4;
    int r0 = 2*ty, c0 = 2*tx;
    float d00 = 0.f, d01 = 0.f, d10 = 0.f, d11 = 0.f;
    #pragma unroll 4
    for (int d = 0; d < 128; d++) {
        float a0 = ea_i[r0][d], a1 = ea_i[r0+1][d];
        float b0 = ea_j[c0][d], b1 = ea_j[c0+1][d];
        d00 += a0*b0; d01 += a0*b1; d10 += a1*b0; d11 += a1*b1;
    }
    float lm = 0.f;
    float dots[4] = {d00, d01, d10, d11};
    #pragma unroll
    for (int u = 0; u < 4; u++) {
        int r = r0 + (u>>1), c = c0 + (u&1);
        float d2 = fmaxf(sqi[r] + sqj[c] - 2.f*dots[u], 0.f);
        float dd = sqrtf(d2 + 1e-12f);
        dout[(i0+r)*1024 + j0 + c] = dd;
        lm = fmaxf(lm, dd);
    }
    #pragma unroll
    for (int o = 16; o; o >>= 1) lm = fmaxf(lm, __shfl_xor_sync(0xffffffffu, lm, o));
    if ((tid&31) == 0) rmax[tid>>5] = lm;
    __syncthreads();
    if (tid == 0) {
        float m = 0.f;
        for (int i = 0; i < 8; i++) m = fmaxf(m, rmax[i]);
        atomicMax(&g_dmax, __float_as_uint(m));
    }
}

__global__ void k_final(float* __restrict__ dout) {
    float inv = 1.f/__uint_as_float(g_dmax);
    int i = blockIdx.x*256 + threadIdx.x;
    dout[i] = 1.f - dout[i]*inv;
}

extern "C" void kernel_launch(void* const* d_in, const int* in_sizes, int n_in,
                              void* d_out, int out_size) {
    const float* x   = (const float*)d_in[0];
    const float* c1w = (const float*)d_in[1];
    const float* c1b = (const float*)d_in[2];
    const float* g1g = (const float*)d_in[3];
    const float* g1b = (const float*)d_in[4];
    const float* c2w = (const float*)d_in[5];
    const float* c2b = (const float*)d_in[6];
    const float* g2g = (const float*)d_in[7];
    const float* g2b = (const float*)d_in[8];
    const float* c3w = (const float*)d_in[9];
    const float* c3b = (const float*)d_in[10];
    const float* g3g = (const float*)d_in[11];
    const float* g3b = (const float*)d_in[12];
    const float* fcw = (const float*)d_in[13];
    const float* fcb = (const float*)d_in[14];
    const float* wq  = (const float*)d_in[15];
    const float* bq  = (const float*)d_in[16];
    const float* wk  = (const float*)d_in[17];
    const float* bk  = (const float*)d_in[18];
    const float* wv  = (const float*)d_in[19];
    const float* bv  = (const float*)d_in[20];
    float* out = (float*)d_out;

    cudaFuncSetAttribute(k_conv2mma, cudaFuncAttributeMaxDynamicSharedMemorySize, C2_SMEM);
    cudaFuncSetAttribute(k_conv3mma4, cudaFuncAttributeMaxDynamicSharedMemorySize, C3_SMEM);

    k_zero<<<1, 256>>>();
    k_prep<<<768, 256>>>(c2w, c3w);
    k_conv1<<<1024, 256>>>(x, c1w, c1b, g1g, g1b);
    k_conv2mma<<<dim3(1024,2), 384, C2_SMEM>>>(c2b, g2g, g2b);
    k_conv3mma4<<<256, 512, C3_SMEM>>>(c3b, g3g, g3b);
    k_fc  <<<128, 256>>>(fcw, fcb);
    k_qkv <<<128, 256>>>(wq, bq, wk, bk, wv, bv);
    k_attn<<<128, 256>>>();
    k_cs1 <<<64, 256>>>();
    k_cs2 <<<64, 256>>>();
    k_cs3r<<<1024, 128>>>();
    k_gram<<<dim3(32,32), 256>>>(out);
    k_final<<<4096, 256>>>(out);
}

// round 14
// speedup vs baseline: 1.0317x; 1.0317x over previous
#include <cuda_runtime.h>
#include <math.h>

#define NS 1024

__device__ float g_h1p[NS*32*36*16];
__device__ float g_h2p[NS*64*12*4];
__device__ float g_h3p[NS*128*4*2];
__device__ float g_w2t[4*192*64];
__device__ float g_w3t[16*96*128];
__device__ float g_e [NS*128];
__device__ float g_q [NS*128];
__device__ float g_k [NS*128];
__device__ float g_v [NS*128];
__device__ float g_ao[NS*128];
__device__ float g_o2[NS*128];
__device__ float g_ea[NS*128];
__device__ float g_sq[NS];
__device__ float g_css[128];
__device__ float g_css2[128];
__device__ unsigned int g_dmax;

__device__ __forceinline__ float selu_f(float x) {
    const float a = 1.6732632423543772f, sc = 1.0507009873554805f;
    return x > 0.f ? sc * x : sc * a * (expf(x) - 1.f);
}

__device__ __forceinline__ float2 ffma2(float2 a, float2 b, float2 c) {
    unsigned long long ua = *(unsigned long long*)&a;
    unsigned long long ub = *(unsigned long long*)&b;
    unsigned long long uc = *(unsigned long long*)&c;
    unsigned long long ud;
    asm("fma.rn.f32x2 %0, %1, %2, %3;" : "=l"(ud) : "l"(ua), "l"(ub), "l"(uc));
    return *(float2*)&ud;
}

__device__ __forceinline__ unsigned tf32c(float x) {
    unsigned u; asm("cvt.rna.tf32.f32 %0, %1;" : "=r"(u) : "f"(x)); return u;
}
__device__ __forceinline__ float tf32f(float x) {
    return __uint_as_float(tf32c(x));
}
__device__ __forceinline__ void mma_tf32(float* d, const unsigned* a, const unsigned* b) {
    asm volatile("mma.sync.aligned.m16n8k8.row.col.f32.tf32.tf32.f32 "
        "{%0,%1,%2,%3}, {%4,%5,%6,%7}, {%8,%9}, {%0,%1,%2,%3};"
        : "+f"(d[0]), "+f"(d[1]), "+f"(d[2]), "+f"(d[3])
        : "r"(a[0]), "r"(a[1]), "r"(a[2]), "r"(a[3]), "r"(b[0]), "r"(b[1]));
}

__global__ void k_zero() {
    int t = threadIdx.x;
    if (t < 128) { g_css[t] = 0.f; g_css2[t] = 0.f; }
    if (t == 255) g_dmax = 0u;
}

__global__ void __launch_bounds__(256) k_prep(const float* __restrict__ w2,
        const float* __restrict__ w3) {
    int i = blockIdx.x*256 + threadIdx.x;
    if (i < 49152)  g_w2t[i] = tf32f(w2[(i&63)*768 + (i>>6)]);
    if (i < 196608) g_w3t[i] = tf32f(w3[(i&127)*1536 + (i>>7)]);
}

// ===== conv1: 1 block/frame, 32 ch (FFMA2). Stores tf32-converted output =====
__global__ void __launch_bounds__(256) k_conv1(const float* __restrict__ x,
        const float* __restrict__ w, const float* __restrict__ bias,
        const float* __restrict__ gg, const float* __restrict__ gb) {
    __shared__ __align__(16) float pad[77*68];
    int s = blockIdx.x, tid = threadIdx.x, lane = tid & 31;
    const float* xs = x + s*4608;
    for (int i = tid; i < 77*68; i += 256) {
        int r = i/68, cc = i - r*68;
        int ih = r-2, iw = cc-1;
        pad[i] = (ih>=0 && ih<72 && iw>=0 && iw<64) ? xs[ih*64+iw] : 0.f;
    }
    __syncthreads();
    for (int cc4 = 0; cc4 < 4; cc4++) {
        int ch = cc4*8 + (tid>>5);
        float2 w2[24];
        #pragma unroll
        for (int k2 = 0; k2 < 24; k2++) { float wv = w[ch*24+k2]; w2[k2] = make_float2(wv, wv); }
        float bi = bias[ch];
        float pm[18], pn[18], sum = 0.f, sq = 0.f;
        for (int wi = 0; wi < 18; wi++) {
            int wdw = wi*32 + lane;
            int ph = wdw>>4, pw = wdw&15;
            float2 acc[2][2];
            #pragma unroll
            for (int r = 0; r < 2; r++)
                #pragma unroll
                for (int cp = 0; cp < 2; cp++) acc[r][cp] = make_float2(bi, bi);
            #pragma unroll
            for (int ir = 0; ir < 7; ir++) {
                const float* pr = &pad[(2*ph+ir)*68 + 4*pw];
                float4 va = *(const float4*)pr;
                float4 vb = *(const float4*)(pr + 4);
                float v[7] = {va.x, va.y, va.z, va.w, vb.x, vb.y, vb.z};
                #pragma unroll
                for (int r = 0; r < 2; r++) {
                    int kh = ir - r;
                    if (kh >= 0 && kh < 6) {
                        #pragma unroll
                        for (int kw = 0; kw < 4; kw++) {
                            float2 wv = w2[kh*4+kw];
                            #pragma unroll
                            for (int cp = 0; cp < 2; cp++)
                                acc[r][cp] = ffma2(make_float2(v[2*cp+kw], v[2*cp+kw+1]), wv, acc[r][cp]);
                        }
                    }
                }
            }
            float mx = -1e30f, mn = 1e30f;
            #pragma unroll
            for (int r = 0; r < 2; r++)
                #pragma unroll
                for (int cp = 0; cp < 2; cp++) {
                    float u0 = selu_f(acc[r][cp].x), u1 = selu_f(acc[r][cp].y);
                    sum += u0+u1; sq += u0*u0+u1*u1;
                    mx = fmaxf(mx, fmaxf(u0,u1)); mn = fminf(mn, fminf(u0,u1));
                }
            pm[wi] = mx; pn[wi] = mn;
        }
        #pragma unroll
        for (int o = 16; o; o >>= 1) {
            sum += __shfl_xor_sync(0xffffffffu, sum, o);
            sq  += __shfl_xor_sync(0xffffffffu, sq , o);
        }
        float mean = sum*(1.f/4608.f);
        float var  = sq*(1.f/4608.f) - mean*mean;
        float sc = gg[ch]*rsqrtf(var+1e-5f);
        float sh = gb[ch] - mean*sc;
        for (int wi = 0; wi < 18; wi++) {
            int wdw = wi*32 + lane;
            int ph = wdw>>4, pw = wdw&15;
            float val = sc>0.f ? pm[wi]*sc+sh : pn[wi]*sc+sh;
            g_h1p[((s*32+ch)*36+ph)*16+pw] = tf32f(val);
        }
    }
}

// ===== conv2: TF32 mma, 384 thr, ws stride 36 (bank-conflict-free A), fused GN+pool =====
#define C2_SMEM (32*577*4)
__global__ void __launch_bounds__(384, 2) k_conv2mma(const float* __restrict__ bias,
        const float* __restrict__ gg, const float* __restrict__ gb) {
    extern __shared__ float dsm[];
    float* ws   = dsm;          // 192 x 36 (tf32 bits) = 6912
    float* padc = dsm + 6912;   // 8 x 779 (tf32 bits)  -> ends 13144 < 18464
    float* cv   = dsm;          // aliased after compute: 32 x 577
    int s = blockIdx.x, ocb = 32*blockIdx.y;
    int tid = threadIdx.x, wrp = tid>>5, t = tid&31;
    int m = wrp & 1, ng = wrp >> 1;       // ng 0..5, 96 n each
    float cfr[12][4];
    #pragma unroll
    for (int j = 0; j < 12; j++) { cfr[j][0]=cfr[j][1]=cfr[j][2]=cfr[j][3]=0.f; }
    int off[12];
    #pragma unroll
    for (int j = 0; j < 12; j++) {
        int n = ng*96 + j*8 + (t>>2);
        off[j] = (n>>4)*19 + (n&15);
    }
    for (int ck = 0; ck < 4; ck++) {
        __syncthreads();
        #pragma unroll
        for (int u = 0; u < 16; u++) {
            int i = tid + u*384;
            ws[(i>>5)*36 + (i&31)] = g_w2t[ck*12288 + (i>>5)*64 + ocb + (i&31)];
        }
        for (int i = tid; i < 6232; i += 384) {
            int icl = i/779, rem = i - icl*779;
            int row = rem/19, col = rem - row*19;
            int ih = row - 2, iw = col - 1;
            padc[i] = (ih>=0 && ih<36 && iw>=0 && iw<16)
                    ? g_h1p[((s*32 + ck*8 + icl)*36 + ih)*16 + iw] : 0.f;
        }
        __syncthreads();
        #pragma unroll 1
        for (int sl = 0; sl < 24; sl++) {
            int icl = sl/3, t8 = (sl - icl*3)*8;
            int kk = icl*24 + t8 + (t&3);
            unsigned A[4];
            A[0] = __float_as_uint(ws[kk*36 + m*16 + (t>>2)]);
            A[1] = __float_as_uint(ws[kk*36 + m*16 + (t>>2) + 8]);
            A[2] = __float_as_uint(ws[(kk+4)*36 + m*16 + (t>>2)]);
            A[3] = __float_as_uint(ws[(kk+4)*36 + m*16 + (t>>2) + 8]);
            const float* pb = padc + icl*779 + (t8>>2)*19 + (t&3);
            #pragma unroll
            for (int j = 0; j < 12; j++) {
                unsigned B[2];
                B[0] = __float_as_uint(pb[off[j]]);
                B[1] = __float_as_uint(pb[off[j] + 19]);
                mma_tf32(cfr[j], A, B);
            }
        }
    }
    __syncthreads();
    int ocl = m*16 + (t>>2);
    float b0v = bias[ocb+ocl], b8v = bias[ocb+ocl+8];
    #pragma unroll
    for (int j = 0; j < 12; j++) {
        int n0 = ng*96 + j*8 + (t&3)*2;
        cv[ocl*577 + n0]     = selu_f(cfr[j][0] + b0v);
        cv[ocl*577 + n0 + 1] = selu_f(cfr[j][1] + b0v);
        cv[(ocl+8)*577 + n0]     = selu_f(cfr[j][2] + b8v);
        cv[(ocl+8)*577 + n0 + 1] = selu_f(cfr[j][3] + b8v);
    }
    __syncthreads();
    if (tid < 256) {
        int g = tid>>4, e = tid&15;
        float sm = 0.f, sq = 0.f;
        #pragma unroll
        for (int cl = 0; cl < 2; cl++)
            for (int i = e; i < 576; i += 16) {
                float v = cv[(2*g+cl)*577 + i];
                sm += v; sq += v*v;
            }
        #pragma unroll
        for (int o = 8; o; o >>= 1) {
            sm += __shfl_xor_sync(0xffffffffu, sm, o);
            sq += __shfl_xor_sync(0xffffffffu, sq, o);
        }
        float mean = sm*(1.f/1152.f);
        float var  = sq*(1.f/1152.f) - mean*mean;
        float inv  = rsqrtf(var + 1e-5f);
        #pragma unroll
        for (int ii = 0; ii < 6; ii++) {
            int u = e + 16*ii;
            int cl = u/48, rem = u - cl*48;
            int ph = rem>>2, pw = rem&3;
            float scv = gg[ocb+2*g+cl]*inv;
            float shv = gb[ocb+2*g+cl] - mean*scv;
            float mx = -1e30f;
            #pragma unroll
            for (int r = 0; r < 3; r++)
                #pragma unroll
                for (int c = 0; c < 4; c++)
                    mx = fmaxf(mx, cv[(2*g+cl)*577 + (3*ph+r)*16 + 4*pw+c]*scv + shv);
            g_h2p[((s*64 + ocb + 2*g + cl)*12 + ph)*4 + pw] = tf32f(mx);
        }
    }
}

// ===== conv3: TF32 mma, 4 frames/block, grid 256, 512 thr, fused GN+pool =====
#define C3_SMEM (96*132*4)
__global__ void __launch_bounds__(512) k_conv3mma4(const float* __restrict__ bias,
        const float* __restrict__ gg, const float* __restrict__ gb) {
    extern __shared__ float ws[];
    __shared__ float pad[4*476];
    float* cv = ws;
    int s4 = blockIdx.x*4, tid = threadIdx.x, wrp = tid>>5, t = tid&31;
    int m = wrp & 7, ng = wrp >> 3;
    float cfr[12][4];
    #pragma unroll
    for (int j = 0; j < 12; j++) { cfr[j][0]=cfr[j][1]=cfr[j][2]=cfr[j][3]=0.f; }
    int off[12];
    #pragma unroll
    for (int j = 0; j < 12; j++) {
        int n = ng*96 + j*8 + (t>>2);
        int f = (ng*96 + j*8)/48;
        int np = n - 48*f;
        off[j] = f*476 + (np>>2)*7 + (np&3);
    }
    for (int ck = 0; ck < 16; ck++) {
        __syncthreads();
        #pragma unroll
        for (int u = 0; u < 6; u++) {
            int i = (tid + u*512)*4;
            float4 wv4 = *(const float4*)&g_w3t[ck*12288 + i];
            *(float4*)&ws[(i>>7)*132 + (i&127)] = wv4;
        }
        for (int i = tid; i < 1904; i += 512) {
            int f = i/476, rem = i - f*476;
            int icl = rem/119, rem2 = rem - icl*119;
            int rr = rem2/7, cc = rem2 - rr*7;
            int ih = rr-2, iw = cc-1;
            pad[i] = (ih>=0 && ih<12 && iw>=0 && iw<4)
                   ? g_h2p[(((s4+f)*64 + ck*4 + icl)*12 + ih)*4 + iw] : 0.f;
        }
        __syncthreads();
        #pragma unroll 1
        for (int sl = 0; sl < 12; sl++) {
            int icl = sl/3, t8 = (sl - icl*3)*8;
            int kk = icl*24 + t8 + (t&3);
            unsigned A[4];
            A[0] = __float_as_uint(ws[kk*132 + m*16 + (t>>2)]);
            A[1] = __float_as_uint(ws[kk*132 + m*16 + (t>>2) + 8]);
            A[2] = __float_as_uint(ws[(kk+4)*132 + m*16 + (t>>2)]);
            A[3] = __float_as_uint(ws[(kk+4)*132 + m*16 + (t>>2) + 8]);
            const float* pb = pad + icl*119 + (t8>>2)*7 + (t&3);
            #pragma unroll
            for (int j = 0; j < 12; j++) {
                unsigned B[2];
                B[0] = __float_as_uint(pb[off[j]]);
                B[1] = __float_as_uint(pb[off[j] + 7]);
                mma_tf32(cfr[j], A, B);
            }
        }
    }
    int oc0 = m*16 + (t>>2);
    float b0v = bias[oc0], b8v = bias[oc0+8];
    for (int f = 0; f < 4; f++) {
        __syncthreads();
        #pragma unroll
        for (int j = 0; j < 12; j++) {
            int fj = ng*2 + j/6;
            if (fj == f) {
                int np = (j - (j/6)*6)*8 + (t&3)*2;
                cv[oc0*49 + np]     = selu_f(cfr[j][0] + b0v);
                cv[oc0*49 + np + 1] = selu_f(cfr[j][1] + b0v);
                cv[(oc0+8)*49 + np]     = selu_f(cfr[j][2] + b8v);
                cv[(oc0+8)*49 + np + 1] = selu_f(cfr[j][3] + b8v);
            }
        }
        __syncthreads();
        int g = tid>>4, e = tid&15;
        float sm = 0.f, sq = 0.f;
        #pragma unroll
        for (int cl = 0; cl < 4; cl++)
            for (int i = e; i < 48; i += 16) {
                float v = cv[(4*g+cl)*49 + i];
                sm += v; sq += v*v;
            }
        #pragma unroll
        for (int o = 8; o; o >>= 1) {
            sm += __shfl_xor_sync(0xffffffffu, sm, o);
            sq += __shfl_xor_sync(0xffffffffu, sq, o);
        }
        float mean = sm*(1.f/192.f);
        float var  = sq*(1.f/192.f) - mean*mean;
        float inv  = rsqrtf(var + 1e-5f);
        #pragma unroll
        for (int ii = 0; ii < 2; ii++) {
            int u = e + 16*ii;
            int cl = u>>3, rem = u&7;
            int ph = rem>>1, pw = rem&1;
            float scv = gg[4*g+cl]*inv;
            float shv = gb[4*g+cl] - mean*scv;
            float mx = -1e30f;
            #pragma unroll
            for (int r = 0; r < 3; r++)
                #pragma unroll
                for (int c = 0; c < 2; c++)
                    mx = fmaxf(mx, cv[(4*g+cl)*49 + (3*ph+r)*4 + 2*pw+c]*scv + shv);
            g_h3p[(((s4+f)*128 + 4*g + cl)*4 + ph)*2 + pw] = mx;
        }
    }
}

// ===== fc =====
__global__ void __launch_bounds__(256) k_fc(const float* __restrict__ w,
        const float* __restrict__ bias) {
    __shared__ float xs[8*65];
    __shared__ float wt[64*129];
    __shared__ float sred[8][4];
    int r0 = blockIdx.x*8, tid = threadIdx.x;
    int c = tid&127, rg = tid>>7, wrp = tid>>5, ln = tid&31;
    float acc[4];
    float b0 = bias[c];
    #pragma unroll
    for (int rr = 0; rr < 4; rr++) acc[rr] = b0;
    for (int k0 = 0; k0 < 1024; k0 += 64) {
        __syncthreads();
        for (int i = tid; i < 512; i += 256) {
            int r = i>>6, kk = i&63;
            xs[r*65+kk] = g_h3p[(r0+r)*1024 + k0 + kk];
        }
        for (int i = tid; i < 8192; i += 256) {
            int j = i>>6, kk = i&63;
            wt[kk*129+j] = w[j*1024 + k0 + kk];
        }
        __syncthreads();
        for (int kk = 0; kk < 64; kk++) {
            float wv = wt[kk*129+c];
            #pragma unroll
            for (int rr = 0; rr < 4; rr++) acc[rr] += xs[(rg*4+rr)*65+kk]*wv;
        }
    }
    float v[4];
    #pragma unroll
    for (int rr = 0; rr < 4; rr++) v[rr] = selu_f(acc[rr]);
    #pragma unroll
    for (int rr = 0; rr < 4; rr++) {
        float ss = v[rr]*v[rr];
        #pragma unroll
        for (int o = 16; o; o >>= 1) ss += __shfl_xor_sync(0xffffffffu, ss, o);
        if (ln == 0) sred[wrp][rr] = ss;
    }
    __syncthreads();
    #pragma unroll
    for (int rr = 0; rr < 4; rr++) {
        float t = sred[rg*4+0][rr] + sred[rg*4+1][rr] + sred[rg*4+2][rr] + sred[rg*4+3][rr];
        float n = fmaxf(sqrtf(t), 1e-12f);
        g_e[(r0+rg*4+rr)*128 + c] = v[rr]/n;
    }
}

// ===== qkv =====
__global__ void __launch_bounds__(256) k_qkv(const float* __restrict__ wq,
        const float* __restrict__ bq, const float* __restrict__ wk,
        const float* __restrict__ bk, const float* __restrict__ wv,
        const float* __restrict__ bv) {
    __shared__ float es[8*132];
    __shared__ float wt[64*129];
    int r0 = blockIdx.x*8, tid = threadIdx.x;
    int c = tid&127, rg = tid>>7;
    for (int i = tid; i < 1024; i += 256) {
        int r = i>>7, d = i&127;
        es[r*132+d] = g_e[(r0+r)*128 + d];
    }
    const float* W[3] = {wq, wk, wv};
    const float* B[3] = {bq, bk, bv};
    float* O[3] = {g_q, g_k, g_v};
    for (int m = 0; m < 3; m++) {
        float acc[4];
        float b0 = B[m][c];
        #pragma unroll
        for (int rr = 0; rr < 4; rr++) acc[rr] = b0;
        for (int k0 = 0; k0 < 128; k0 += 64) {
            __syncthreads();
            for (int i = tid; i < 8192; i += 256) {
                int j = i>>6, kk = i&63;
                wt[kk*129+j] = W[m][j*128 + k0 + kk];
            }
            __syncthreads();
            for (int kk = 0; kk < 64; kk++) {
                float wvv = wt[kk*129+c];
                #pragma unroll
                for (int rr = 0; rr < 4; rr++) acc[rr] += es[(rg*4+rr)*132 + k0 + kk]*wvv;
            }
        }
        #pragma unroll
        for (int rr = 0; rr < 4; rr++) {
            int sr = r0 + rg*4 + rr;
            float u = selu_f(acc[rr]);
            if (m == 1) {
                float f = expf((float)(c & ~1) * (-9.210340371976184f/128.f));
                float ang = (float)sr * f;
                u += (c & 1) ? cosf(ang) : sinf(ang);
            }
            O[m][sr*128 + c] = u;
        }
    }
}

// ===== attn =====
__global__ void __launch_bounds__(256) k_attn() {
    __shared__ __align__(16) float q8[8*132];
    __shared__ __align__(16) float p[8*1024];
    __shared__ float rinv[8];
    int r0 = blockIdx.x*8, tid = threadIdx.x;
    for (int i = tid; i < 1024; i += 256) {
        int r = i>>7, d = i&127;
        q8[r*132+d] = g_q[(r0+r)*128 + d];
    }
    __syncthreads();
    const float scale = 0.08838834764831845f;
    for (int t = tid; t < 1024; t += 256) {
        float2 a2[8];
        #pragma unroll
        for (int r = 0; r < 8; r++) a2[r] = make_float2(0.f, 0.f);
        const float4* kr = (const float4*)(g_k + t*128);
        #pragma unroll 4
        for (int d4 = 0; d4 < 32; d4++) {
            float4 kv = kr[d4];
            float2 klo = make_float2(kv.x, kv.y), khi = make_float2(kv.z, kv.w);
            #pragma unroll
            for (int r = 0; r < 8; r++) {
                float4 qv = *(const float4*)&q8[r*132 + d4*4];
                a2[r] = ffma2(make_float2(qv.x, qv.y), klo, a2[r]);
                a2[r] = ffma2(make_float2(qv.z, qv.w), khi, a2[r]);
            }
        }
        #pragma unroll
        for (int r = 0; r < 8; r++) p[r*1024+t] = (a2[r].x + a2[r].y)*scale;
    }
    __syncthreads();
    int wrp = tid>>5, ln = tid&31;
    {
        int r = wrp;
        float mxv = -1e30f;
        for (int t = ln; t < 1024; t += 32) mxv = fmaxf(mxv, p[r*1024+t]);
        #pragma unroll
        for (int o = 16; o; o >>= 1) mxv = fmaxf(mxv, __shfl_xor_sync(0xffffffffu, mxv, o));
        float sm = 0.f;
        for (int t = ln; t < 1024; t += 32) {
            float e = expf(p[r*1024+t] - mxv);
            p[r*1024+t] = e;
            sm += e;
        }
        #pragma unroll
        for (int o = 16; o; o >>= 1) sm += __shfl_xor_sync(0xffffffffu, sm, o);
        if (ln == 0) rinv[r] = 1.f/sm;
    }
    __syncthreads();
    int c2 = tid&63, hf = tid>>6;
    float2 acc2[8];
    #pragma unroll
    for (int r = 0; r < 8; r++) acc2[r] = make_float2(0.f, 0.f);
    for (int t = hf*256; t < hf*256+256; t++) {
        float2 vv = *(const float2*)&g_v[t*128 + 2*c2];
        #pragma unroll
        for (int r = 0; r < 8; r++) {
            float pv = p[r*1024+t];
            acc2[r] = ffma2(make_float2(pv, pv), vv, acc2[r]);
        }
    }
    __syncthreads();
    float2* pbuf = (float2*)p;
    if (hf) {
        #pragma unroll
        for (int r = 0; r < 8; r++) pbuf[(hf-1)*512 + r*64 + c2] = acc2[r];
    }
    __syncthreads();
    if (hf == 0) {
        #pragma unroll
        for (int r = 0; r < 8; r++) {
            float2 sv = acc2[r];
            #pragma unroll
            for (int q = 0; q < 3; q++) {
                float2 o = pbuf[q*512 + r*64 + c2];
                sv.x += o.x; sv.y += o.y;
            }
            g_ao[(r0+r)*128 + 2*c2]     = sv.x*rinv[r];
            g_ao[(r0+r)*128 + 2*c2 + 1] = sv.y*rinv[r];
        }
    }
}

__global__ void __launch_bounds__(256) k_cs1() {
    __shared__ float red[128];
    int s0 = blockIdx.x*16, tid = threadIdx.x;
    int c = tid&127, sy = tid>>7;
    float ss = 0.f;
    for (int s = sy; s < 16; s += 2) { float v = g_ao[(s0+s)*128+c]; ss += v*v; }
    if (sy) red[c] = ss;
    __syncthreads();
    if (!sy) atomicAdd(&g_css[c], ss + red[c]);
}

__global__ void __launch_bounds__(256) k_cs2() {
    __shared__ float red[128];
    int s0 = blockIdx.x*16, tid = threadIdx.x;
    int c = tid&127, sy = tid>>7;
    float inv1 = 1.f/fmaxf(sqrtf(g_css[c]), 1e-12f);
    float ss = 0.f;
    for (int s = sy; s < 16; s += 2) {
        float v = g_ao[(s0+s)*128+c]*inv1 + g_e[(s0+s)*128+c];
        g_o2[(s0+s)*128+c] = v;
        ss += v*v;
    }
    if (sy) red[c] = ss;
    __syncthreads();
    if (!sy) atomicAdd(&g_css2[c], ss + red[c]);
}

__global__ void __launch_bounds__(128) k_cs3r() {
    __shared__ float red[4];
    int s = blockIdx.x, d = threadIdx.x;
    int wrp = d>>5, ln = d&31;
    float inv2 = 1.f/fmaxf(sqrtf(g_css2[d]), 1e-12f);
    float v = g_o2[s*128+d]*inv2;
    g_ea[s*128+d] = v;
    float ss = v*v;
    #pragma unroll
    for (int o = 16; o; o >>= 1) ss += __shfl_xor_sync(0xffffffffu, ss, o);
    if (ln == 0) red[wrp] = ss;
    __syncthreads();
    if (d == 0) g_sq[s] = red[0]+red[1]+red[2]+red[3];
}

__global__ void k_gram(float* __restrict__ dout) {
    __shared__ float ea_i[32][129];
    __shared__ float ea_j[32][129];
    __shared__ float sqi[32], sqj[32];
    __shared__ float rmax[8];
    int i0 = blockIdx.y*32, j0 = blockIdx.x*32;
    int tid = threadIdx.x;
    for (int idx = tid; idx < 4096; idx += 256) {
        int r = idx>>7, d = idx&127;
        ea_i[r][d] = g_ea[(i0+r)*128+d];
        ea_j[r][d] = g_ea[(j0+r)*128+d];
    }
    if (tid < 32) { sqi[tid] = g_sq[i0+tid]; sqj[tid] = g_sq[j0+tid]; }
    __syncthreads();
    int tx = tid&15, ty = tid>>4;
    int r0 = 2*ty, c0 = 2*tx;
    float d00 = 0.f, d01 = 0.f, d10 = 0.f, d11 = 0.f;
    #pragma unroll 4
    for (int d = 0; d < 128; d++) {
        float a0 = ea_i[r0][d], a1 = ea_i[r0+1][d];
        float b0 = ea_j[c0][d], b1 = ea_j[c0+1][d];
        d00 += a0*b0; d01 += a0*b1; d10 += a1*b0; d11 += a1*b1;
    }
    float lm = 0.f;
    float dots[4] = {d00, d01, d10, d11};
    #pragma unroll
    for (int u = 0; u < 4; u++) {
        int r = r0 + (u>>1), c = c0 + (u&1);
        float d2 = fmaxf(sqi[r] + sqj[c] - 2.f*dots[u], 0.f);
        float dd = sqrtf(d2 + 1e-12f);
        dout[(i0+r)*1024 + j0 + c] = dd;
        lm = fmaxf(lm, dd);
    }
    #pragma unroll
    for (int o = 16; o; o >>= 1) lm = fmaxf(lm, __shfl_xor_sync(0xffffffffu, lm, o));
    if ((tid&31) == 0) rmax[tid>>5] = lm;
    __syncthreads();
    if (tid == 0) {
        float m = 0.f;
        for (int i = 0; i < 8; i++) m = fmaxf(m, rmax[i]);
        atomicMax(&g_dmax, __float_as_uint(m));
    }
}

__global__ void k_final(float* __restrict__ dout) {
    float inv = 1.f/__uint_as_float(g_dmax);
    int i = blockIdx.x*256 + threadIdx.x;
    dout[i] = 1.f - dout[i]*inv;
}

extern "C" void kernel_launch(void* const* d_in, const int* in_sizes, int n_in,
                              void* d_out, int out_size) {
    const float* x   = (const float*)d_in[0];
    const float* c1w = (const float*)d_in[1];
    const float* c1b = (const float*)d_in[2];
    const float* g1g = (const float*)d_in[3];
    const float* g1b = (const float*)d_in[4];
    const float* c2w = (const float*)d_in[5];
    const float* c2b = (const float*)d_in[6];
    const float* g2g = (const float*)d_in[7];
    const float* g2b = (const float*)d_in[8];
    const float* c3w = (const float*)d_in[9];
    const float* c3b = (const float*)d_in[10];
    const float* g3g = (const float*)d_in[11];
    const float* g3b = (const float*)d_in[12];
    const float* fcw = (const float*)d_in[13];
    const float* fcb = (const float*)d_in[14];
    const float* wq  = (const float*)d_in[15];
    const float* bq  = (const float*)d_in[16];
    const float* wk  = (const float*)d_in[17];
    const float* bk  = (const float*)d_in[18];
    const float* wv  = (const float*)d_in[19];
    const float* bv  = (const float*)d_in[20];
    float* out = (float*)d_out;

    cudaFuncSetAttribute(k_conv2mma, cudaFuncAttributeMaxDynamicSharedMemorySize, C2_SMEM);
    cudaFuncSetAttribute(k_conv3mma4, cudaFuncAttributeMaxDynamicSharedMemorySize, C3_SMEM);

    k_zero<<<1, 256>>>();
    k_prep<<<768, 256>>>(c2w, c3w);
    k_conv1<<<1024, 256>>>(x, c1w, c1b, g1g, g1b);
    k_conv2mma<<<dim3(1024,2), 384, C2_SMEM>>>(c2b, g2g, g2b);
    k_conv3mma4<<<256, 512, C3_SMEM>>>(c3b, g3g, g3b);
    k_fc  <<<128, 256>>>(fcw, fcb);
    k_qkv <<<128, 256>>>(wq, bq, wk, bk, wv, bv);
    k_attn<<<128, 256>>>();
    k_cs1 <<<64, 256>>>();
    k_cs2 <<<64, 256>>>();
    k_cs3r<<<1024, 128>>>();
    k_gram<<<dim3(32,32), 256>>>(out);
    k_final<<<4096, 256>>>(out);
}

// round 15
// speedup vs baseline: 1.0823x; 1.0491x over previous
#include <cuda_runtime.h>
#include <math.h>

#define NS 1024

__device__ float g_h1p[NS*32*36*16];
__device__ float g_h2p[NS*64*12*4];
__device__ float g_h3p[NS*128*4*2];
__device__ float g_w2t[4*192*64];
__device__ float g_w3t[16*96*128];
__device__ float g_e [NS*128];
__device__ float g_q [NS*128];
__device__ float g_k [NS*128];
__device__ float g_v [NS*128];
__device__ float g_ao[NS*128];
__device__ float g_o2[NS*128];
__device__ float g_ea[NS*128];
__device__ float g_sq[NS];
__device__ float g_css[128];
__device__ float g_css2[128];
__device__ unsigned int g_dmax;

__device__ __forceinline__ float selu_f(float x) {
    const float a = 1.6732632423543772f, sc = 1.0507009873554805f;
    return x > 0.f ? sc * x : sc * a * (expf(x) - 1.f);
}

__device__ __forceinline__ float2 ffma2(float2 a, float2 b, float2 c) {
    unsigned long long ua = *(unsigned long long*)&a;
    unsigned long long ub = *(unsigned long long*)&b;
    unsigned long long uc = *(unsigned long long*)&c;
    unsigned long long ud;
    asm("fma.rn.f32x2 %0, %1, %2, %3;" : "=l"(ud) : "l"(ua), "l"(ub), "l"(uc));
    return *(float2*)&ud;
}

__device__ __forceinline__ unsigned tf32c(float x) {
    unsigned u; asm("cvt.rna.tf32.f32 %0, %1;" : "=r"(u) : "f"(x)); return u;
}
__device__ __forceinline__ float tf32f(float x) {
    return __uint_as_float(tf32c(x));
}
__device__ __forceinline__ void mma_tf32(float* d, const unsigned* a, const unsigned* b) {
    asm volatile("mma.sync.aligned.m16n8k8.row.col.f32.tf32.tf32.f32 "
        "{%0,%1,%2,%3}, {%4,%5,%6,%7}, {%8,%9}, {%0,%1,%2,%3};"
        : "+f"(d[0]), "+f"(d[1]), "+f"(d[2]), "+f"(d[3])
        : "r"(a[0]), "r"(a[1]), "r"(a[2]), "r"(a[3]), "r"(b[0]), "r"(b[1]));
}

__device__ __forceinline__ unsigned s2u(const void* p) {
    return (unsigned)__cvta_generic_to_shared(p);
}
__device__ __forceinline__ void cpa4(void* dst, const void* src, int sz) {
    asm volatile("cp.async.ca.shared.global [%0], [%1], 4, %2;"
                 :: "r"(s2u(dst)), "l"(src), "r"(sz));
}
__device__ __forceinline__ void cpa16(void* dst, const void* src) {
    asm volatile("cp.async.cg.shared.global [%0], [%1], 16;"
                 :: "r"(s2u(dst)), "l"(src));
}
__device__ __forceinline__ void cpa_commit() { asm volatile("cp.async.commit_group;"); }
template<int N> __device__ __forceinline__ void cpa_wait() {
    asm volatile("cp.async.wait_group %0;" :: "n"(N));
}

__global__ void k_zero() {
    int t = threadIdx.x;
    if (t < 128) { g_css[t] = 0.f; g_css2[t] = 0.f; }
    if (t == 255) g_dmax = 0u;
}

__global__ void __launch_bounds__(256) k_prep(const float* __restrict__ w2,
        const float* __restrict__ w3) {
    int i = blockIdx.x*256 + threadIdx.x;
    if (i < 49152)  g_w2t[i] = tf32f(w2[(i&63)*768 + (i>>6)]);
    if (i < 196608) g_w3t[i] = tf32f(w3[(i&127)*1536 + (i>>7)]);
}

// ===== conv1: 1 block/frame, 32 ch (FFMA2). Stores tf32-converted output =====
__global__ void __launch_bounds__(256) k_conv1(const float* __restrict__ x,
        const float* __restrict__ w, const float* __restrict__ bias,
        const float* __restrict__ gg, const float* __restrict__ gb) {
    __shared__ __align__(16) float pad[77*68];
    int s = blockIdx.x, tid = threadIdx.x, lane = tid & 31;
    const float* xs = x + s*4608;
    for (int i = tid; i < 77*68; i += 256) {
        int r = i/68, cc = i - r*68;
        int ih = r-2, iw = cc-1;
        pad[i] = (ih>=0 && ih<72 && iw>=0 && iw<64) ? xs[ih*64+iw] : 0.f;
    }
    __syncthreads();
    for (int cc4 = 0; cc4 < 4; cc4++) {
        int ch = cc4*8 + (tid>>5);
        float2 w2[24];
        #pragma unroll
        for (int k2 = 0; k2 < 24; k2++) { float wv = w[ch*24+k2]; w2[k2] = make_float2(wv, wv); }
        float bi = bias[ch];
        float pm[18], pn[18], sum = 0.f, sq = 0.f;
        for (int wi = 0; wi < 18; wi++) {
            int wdw = wi*32 + lane;
            int ph = wdw>>4, pw = wdw&15;
            float2 acc[2][2];
            #pragma unroll
            for (int r = 0; r < 2; r++)
                #pragma unroll
                for (int cp = 0; cp < 2; cp++) acc[r][cp] = make_float2(bi, bi);
            #pragma unroll
            for (int ir = 0; ir < 7; ir++) {
                const float* pr = &pad[(2*ph+ir)*68 + 4*pw];
                float4 va = *(const float4*)pr;
                float4 vb = *(const float4*)(pr + 4);
                float v[7] = {va.x, va.y, va.z, va.w, vb.x, vb.y, vb.z};
                #pragma unroll
                for (int r = 0; r < 2; r++) {
                    int kh = ir - r;
                    if (kh >= 0 && kh < 6) {
                        #pragma unroll
                        for (int kw = 0; kw < 4; kw++) {
                            float2 wv = w2[kh*4+kw];
                            #pragma unroll
                            for (int cp = 0; cp < 2; cp++)
                                acc[r][cp] = ffma2(make_float2(v[2*cp+kw], v[2*cp+kw+1]), wv, acc[r][cp]);
                        }
                    }
                }
            }
            float mx = -1e30f, mn = 1e30f;
            #pragma unroll
            for (int r = 0; r < 2; r++)
                #pragma unroll
                for (int cp = 0; cp < 2; cp++) {
                    float u0 = selu_f(acc[r][cp].x), u1 = selu_f(acc[r][cp].y);
                    sum += u0+u1; sq += u0*u0+u1*u1;
                    mx = fmaxf(mx, fmaxf(u0,u1)); mn = fminf(mn, fminf(u0,u1));
                }
            pm[wi] = mx; pn[wi] = mn;
        }
        #pragma unroll
        for (int o = 16; o; o >>= 1) {
            sum += __shfl_xor_sync(0xffffffffu, sum, o);
            sq  += __shfl_xor_sync(0xffffffffu, sq , o);
        }
        float mean = sum*(1.f/4608.f);
        float var  = sq*(1.f/4608.f) - mean*mean;
        float sc = gg[ch]*rsqrtf(var+1e-5f);
        float sh = gb[ch] - mean*sc;
        for (int wi = 0; wi < 18; wi++) {
            int wdw = wi*32 + lane;
            int ph = wdw>>4, pw = wdw&15;
            float val = sc>0.f ? pm[wi]*sc+sh : pn[wi]*sc+sh;
            g_h1p[((s*32+ch)*36+ph)*16+pw] = tf32f(val);
        }
    }
}

// ===== conv2: TF32 mma, cp.async double-buffered staging, fused GN+pool =====
// stage = ws[192*36]=6912 + pad[6232] = 13144 floats; two stages; cv[32*577] aliases dsm
#define C2_STG 13144
#define C2_SMEM (2*C2_STG*4)
__global__ void __launch_bounds__(384, 2) k_conv2mma(const float* __restrict__ bias,
        const float* __restrict__ gg, const float* __restrict__ gb) {
    extern __shared__ float dsm[];
    float* cv = dsm;
    int s = blockIdx.x, ocb = 32*blockIdx.y;
    int tid = threadIdx.x, wrp = tid>>5, t = tid&31;
    int m = wrp & 1, ng = wrp >> 1;
    float cfr[12][4];
    #pragma unroll
    for (int j = 0; j < 12; j++) { cfr[j][0]=cfr[j][1]=cfr[j][2]=cfr[j][3]=0.f; }
    int off[12];
    #pragma unroll
    for (int j = 0; j < 12; j++) {
        int n = ng*96 + j*8 + (t>>2);
        off[j] = (n>>4)*19 + (n&15);
    }
    // stage chunk ck into buffer
    auto stage = [&](int ck, float* buf) {
        float* wsb = buf;
        float* padb = buf + 6912;
        #pragma unroll
        for (int u = 0; u < 16; u++) {
            int i = tid + u*384;
            cpa4(&wsb[(i>>5)*36 + (i&31)],
                 &g_w2t[ck*12288 + (i>>5)*64 + ocb + (i&31)], 4);
        }
        for (int i = tid; i < 6232; i += 384) {
            int icl = i/779, rem = i - icl*779;
            int row = rem/19, col = rem - row*19;
            int ih = row - 2, iw = col - 1;
            bool ok = (ih>=0 && ih<36 && iw>=0 && iw<16);
            cpa4(&padb[i],
                 &g_h1p[((s*32 + ck*8 + icl)*36 + (ok?ih:0))*16 + (ok?iw:0)],
                 ok ? 4 : 0);
        }
        cpa_commit();
    };
    stage(0, dsm);
    for (int ck = 0; ck < 4; ck++) {
        if (ck > 0) __syncthreads();              // mma(ck-1) done before overwriting its buffer
        if (ck < 3) stage(ck+1, dsm + ((ck+1)&1)*C2_STG);
        if (ck < 3) cpa_wait<1>(); else cpa_wait<0>();
        __syncthreads();
        const float* ws   = dsm + (ck&1)*C2_STG;
        const float* padc = ws + 6912;
        #pragma unroll 1
        for (int sl = 0; sl < 24; sl++) {
            int icl = sl/3, t8 = (sl - icl*3)*8;
            int kk = icl*24 + t8 + (t&3);
            unsigned A[4];
            A[0] = __float_as_uint(ws[kk*36 + m*16 + (t>>2)]);
            A[1] = __float_as_uint(ws[kk*36 + m*16 + (t>>2) + 8]);
            A[2] = __float_as_uint(ws[(kk+4)*36 + m*16 + (t>>2)]);
            A[3] = __float_as_uint(ws[(kk+4)*36 + m*16 + (t>>2) + 8]);
            const float* pb = padc + icl*779 + (t8>>2)*19 + (t&3);
            #pragma unroll
            for (int j = 0; j < 12; j++) {
                unsigned B[2];
                B[0] = __float_as_uint(pb[off[j]]);
                B[1] = __float_as_uint(pb[off[j] + 19]);
                mma_tf32(cfr[j], A, B);
            }
        }
    }
    __syncthreads();
    int ocl = m*16 + (t>>2);
    float b0v = bias[ocb+ocl], b8v = bias[ocb+ocl+8];
    #pragma unroll
    for (int j = 0; j < 12; j++) {
        int n0 = ng*96 + j*8 + (t&3)*2;
        cv[ocl*577 + n0]     = selu_f(cfr[j][0] + b0v);
        cv[ocl*577 + n0 + 1] = selu_f(cfr[j][1] + b0v);
        cv[(ocl+8)*577 + n0]     = selu_f(cfr[j][2] + b8v);
        cv[(ocl+8)*577 + n0 + 1] = selu_f(cfr[j][3] + b8v);
    }
    __syncthreads();
    if (tid < 256) {
        int g = tid>>4, e = tid&15;
        float sm = 0.f, sq = 0.f;
        #pragma unroll
        for (int cl = 0; cl < 2; cl++)
            for (int i = e; i < 576; i += 16) {
                float v = cv[(2*g+cl)*577 + i];
                sm += v; sq += v*v;
            }
        #pragma unroll
        for (int o = 8; o; o >>= 1) {
            sm += __shfl_xor_sync(0xffffffffu, sm, o);
            sq += __shfl_xor_sync(0xffffffffu, sq, o);
        }
        float mean = sm*(1.f/1152.f);
        float var  = sq*(1.f/1152.f) - mean*mean;
        float inv  = rsqrtf(var + 1e-5f);
        #pragma unroll
        for (int ii = 0; ii < 6; ii++) {
            int u = e + 16*ii;
            int cl = u/48, rem = u - cl*48;
            int ph = rem>>2, pw = rem&3;
            float scv = gg[ocb+2*g+cl]*inv;
            float shv = gb[ocb+2*g+cl] - mean*scv;
            float mx = -1e30f;
            #pragma unroll
            for (int r = 0; r < 3; r++)
                #pragma unroll
                for (int c = 0; c < 4; c++)
                    mx = fmaxf(mx, cv[(2*g+cl)*577 + (3*ph+r)*16 + 4*pw+c]*scv + shv);
            g_h2p[((s*64 + ocb + 2*g + cl)*12 + ph)*4 + pw] = tf32f(mx);
        }
    }
}

// ===== conv3: TF32 mma, 4 frames/block, cp.async double-buffered, fused GN+pool =====
// stage = ws[96*132]=12672 + pad[1904] = 14576 floats; two stages; cv[128*49] aliases dsm
#define C3_STG 14576
#define C3_SMEM (2*C3_STG*4)
__global__ void __launch_bounds__(512) k_conv3mma4(const float* __restrict__ bias,
        const float* __restrict__ gg, const float* __restrict__ gb) {
    extern __shared__ float dsm3[];
    float* cv = dsm3;
    int s4 = blockIdx.x*4, tid = threadIdx.x, wrp = tid>>5, t = tid&31;
    int m = wrp & 7, ng = wrp >> 3;
    float cfr[12][4];
    #pragma unroll
    for (int j = 0; j < 12; j++) { cfr[j][0]=cfr[j][1]=cfr[j][2]=cfr[j][3]=0.f; }
    int off[12];
    #pragma unroll
    for (int j = 0; j < 12; j++) {
        int n = ng*96 + j*8 + (t>>2);
        int f = (ng*96 + j*8)/48;
        int np = n - 48*f;
        off[j] = f*476 + (np>>2)*7 + (np&3);
    }
    auto stage = [&](int ck, float* buf) {
        float* wsb = buf;
        float* padb = buf + 12672;
        #pragma unroll
        for (int u = 0; u < 6; u++) {
            int i = (tid + u*512)*4;
            cpa16(&wsb[(i>>7)*132 + (i&127)], &g_w3t[ck*12288 + i]);
        }
        for (int i = tid; i < 1904; i += 512) {
            int f = i/476, rem = i - f*476;
            int icl = rem/119, rem2 = rem - icl*119;
            int rr = rem2/7, cc = rem2 - rr*7;
            int ih = rr-2, iw = cc-1;
            bool ok = (ih>=0 && ih<12 && iw>=0 && iw<4);
            cpa4(&padb[i],
                 &g_h2p[(((s4+f)*64 + ck*4 + icl)*12 + (ok?ih:0))*4 + (ok?iw:0)],
                 ok ? 4 : 0);
        }
        cpa_commit();
    };
    stage(0, dsm3);
    for (int ck = 0; ck < 16; ck++) {
        if (ck > 0) __syncthreads();
        if (ck < 15) stage(ck+1, dsm3 + ((ck+1)&1)*C3_STG);
        if (ck < 15) cpa_wait<1>(); else cpa_wait<0>();
        __syncthreads();
        const float* ws  = dsm3 + (ck&1)*C3_STG;
        const float* pad = ws + 12672;
        #pragma unroll 1
        for (int sl = 0; sl < 12; sl++) {
            int icl = sl/3, t8 = (sl - icl*3)*8;
            int kk = icl*24 + t8 + (t&3);
            unsigned A[4];
            A[0] = __float_as_uint(ws[kk*132 + m*16 + (t>>2)]);
            A[1] = __float_as_uint(ws[kk*132 + m*16 + (t>>2) + 8]);
            A[2] = __float_as_uint(ws[(kk+4)*132 + m*16 + (t>>2)]);
            A[3] = __float_as_uint(ws[(kk+4)*132 + m*16 + (t>>2) + 8]);
            const float* pb = pad + icl*119 + (t8>>2)*7 + (t&3);
            #pragma unroll
            for (int j = 0; j < 12; j++) {
                unsigned B[2];
                B[0] = __float_as_uint(pb[off[j]]);
                B[1] = __float_as_uint(pb[off[j] + 7]);
                mma_tf32(cfr[j], A, B);
            }
        }
    }
    int oc0 = m*16 + (t>>2);
    float b0v = bias[oc0], b8v = bias[oc0+8];
    for (int f = 0; f < 4; f++) {
        __syncthreads();
        #pragma unroll
        for (int j = 0; j < 12; j++) {
            int fj = ng*2 + j/6;
            if (fj == f) {
                int np = (j - (j/6)*6)*8 + (t&3)*2;
                cv[oc0*49 + np]     = selu_f(cfr[j][0] + b0v);
                cv[oc0*49 + np + 1] = selu_f(cfr[j][1] + b0v);
                cv[(oc0+8)*49 + np]     = selu_f(cfr[j][2] + b8v);
                cv[(oc0+8)*49 + np + 1] = selu_f(cfr[j][3] + b8v);
            }
        }
        __syncthreads();
        int g = tid>>4, e = tid&15;
        float sm = 0.f, sq = 0.f;
        #pragma unroll
        for (int cl = 0; cl < 4; cl++)
            for (int i = e; i < 48; i += 16) {
                float v = cv[(4*g+cl)*49 + i];
                sm += v; sq += v*v;
            }
        #pragma unroll
        for (int o = 8; o; o >>= 1) {
            sm += __shfl_xor_sync(0xffffffffu, sm, o);
            sq += __shfl_xor_sync(0xffffffffu, sq, o);
        }
        float mean = sm*(1.f/192.f);
        float var  = sq*(1.f/192.f) - mean*mean;
        float inv  = rsqrtf(var + 1e-5f);
        #pragma unroll
        for (int ii = 0; ii < 2; ii++) {
            int u = e + 16*ii;
            int cl = u>>3, rem = u&7;
            int ph = rem>>1, pw = rem&1;
            float scv = gg[4*g+cl]*inv;
            float shv = gb[4*g+cl] - mean*scv;
            float mx = -1e30f;
            #pragma unroll
            for (int r = 0; r < 3; r++)
                #pragma unroll
                for (int c = 0; c < 2; c++)
                    mx = fmaxf(mx, cv[(4*g+cl)*49 + (3*ph+r)*4 + 2*pw+c]*scv + shv);
            g_h3p[(((s4+f)*128 + 4*g + cl)*4 + ph)*2 + pw] = mx;
        }
    }
}

// ===== fc =====
__global__ void __launch_bounds__(256) k_fc(const float* __restrict__ w,
        const float* __restrict__ bias) {
    __shared__ float xs[8*65];
    __shared__ float wt[64*129];
    __shared__ float sred[8][4];
    int r0 = blockIdx.x*8, tid = threadIdx.x;
    int c = tid&127, rg = tid>>7, wrp = tid>>5, ln = tid&31;
    float acc[4];
    float b0 = bias[c];
    #pragma unroll
    for (int rr = 0; rr < 4; rr++) acc[rr] = b0;
    for (int k0 = 0; k0 < 1024; k0 += 64) {
        __syncthreads();
        for (int i = tid; i < 512; i += 256) {
            int r = i>>6, kk = i&63;
            xs[r*65+kk] = g_h3p[(r0+r)*1024 + k0 + kk];
        }
        for (int i = tid; i < 8192; i += 256) {
            int j = i>>6, kk = i&63;
            wt[kk*129+j] = w[j*1024 + k0 + kk];
        }
        __syncthreads();
        for (int kk = 0; kk < 64; kk++) {
            float wv = wt[kk*129+c];
            #pragma unroll
            for (int rr = 0; rr < 4; rr++) acc[rr] += xs[(rg*4+rr)*65+kk]*wv;
        }
    }
    float v[4];
    #pragma unroll
    for (int rr = 0; rr < 4; rr++) v[rr] = selu_f(acc[rr]);
    #pragma unroll
    for (int rr = 0; rr < 4; rr++) {
        float ss = v[rr]*v[rr];
        #pragma unroll
        for (int o = 16; o; o >>= 1) ss += __shfl_xor_sync(0xffffffffu, ss, o);
        if (ln == 0) sred[wrp][rr] = ss;
    }
    __syncthreads();
    #pragma unroll
    for (int rr = 0; rr < 4; rr++) {
        float t = sred[rg*4+0][rr] + sred[rg*4+1][rr] + sred[rg*4+2][rr] + sred[rg*4+3][rr];
        float n = fmaxf(sqrtf(t), 1e-12f);
        g_e[(r0+rg*4+rr)*128 + c] = v[rr]/n;
    }
}

// ===== qkv =====
__global__ void __launch_bounds__(256) k_qkv(const float* __restrict__ wq,
        const float* __restrict__ bq, const float* __restrict__ wk,
        const float* __restrict__ bk, const float* __restrict__ wv,
        const float* __restrict__ bv) {
    __shared__ float es[8*132];
    __shared__ float wt[64*129];
    int r0 = blockIdx.x*8, tid = threadIdx.x;
    int c = tid&127, rg = tid>>7;
    for (int i = tid; i < 1024; i += 256) {
        int r = i>>7, d = i&127;
        es[r*132+d] = g_e[(r0+r)*128 + d];
    }
    const float* W[3] = {wq, wk, wv};
    const float* B[3] = {bq, bk, bv};
    float* O[3] = {g_q, g_k, g_v};
    for (int m = 0; m < 3; m++) {
        float acc[4];
        float b0 = B[m][c];
        #pragma unroll
        for (int rr = 0; rr < 4; rr++) acc[rr] = b0;
        for (int k0 = 0; k0 < 128; k0 += 64) {
            __syncthreads();
            for (int i = tid; i < 8192; i += 256) {
                int j = i>>6, kk = i&63;
                wt[kk*129+j] = W[m][j*128 + k0 + kk];
            }
            __syncthreads();
            for (int kk = 0; kk < 64; kk++) {
                float wvv = wt[kk*129+c];
                #pragma unroll
                for (int rr = 0; rr < 4; rr++) acc[rr] += es[(rg*4+rr)*132 + k0 + kk]*wvv;
            }
        }
        #pragma unroll
        for (int rr = 0; rr < 4; rr++) {
            int sr = r0 + rg*4 + rr;
            float u = selu_f(acc[rr]);
            if (m == 1) {
                float f = expf((float)(c & ~1) * (-9.210340371976184f/128.f));
                float ang = (float)sr * f;
                u += (c & 1) ? cosf(ang) : sinf(ang);
            }
            O[m][sr*128 + c] = u;
        }
    }
}

// ===== attn =====
__global__ void __launch_bounds__(256) k_attn() {
    __shared__ __align__(16) float q8[8*132];
    __shared__ __align__(16) float p[8*1024];
    __shared__ float rinv[8];
    int r0 = blockIdx.x*8, tid = threadIdx.x;
    for (int i = tid; i < 1024; i += 256) {
        int r = i>>7, d = i&127;
        q8[r*132+d] = g_q[(r0+r)*128 + d];
    }
    __syncthreads();
    const float scale = 0.08838834764831845f;
    for (int t = tid; t < 1024; t += 256) {
        float2 a2[8];
        #pragma unroll
        for (int r = 0; r < 8; r++) a2[r] = make_float2(0.f, 0.f);
        const float4* kr = (const float4*)(g_k + t*128);
        #pragma unroll 4
        for (int d4 = 0; d4 < 32; d4++) {
            float4 kv = kr[d4];
            float2 klo = make_float2(kv.x, kv.y), khi = make_float2(kv.z, kv.w);
            #pragma unroll
            for (int r = 0; r < 8; r++) {
                float4 qv = *(const float4*)&q8[r*132 + d4*4];
                a2[r] = ffma2(make_float2(qv.x, qv.y), klo, a2[r]);
                a2[r] = ffma2(make_float2(qv.z, qv.w), khi, a2[r]);
            }
        }
        #pragma unroll
        for (int r = 0; r < 8; r++) p[r*1024+t] = (a2[r].x + a2[r].y)*scale;
    }
    __syncthreads();
    int wrp = tid>>5, ln = tid&31;
    {
        int r = wrp;
        float mxv = -1e30f;
        for (int t = ln; t < 1024; t += 32) mxv = fmaxf(mxv, p[r*1024+t]);
        #pragma unroll
        for (int o = 16; o; o >>= 1) mxv = fmaxf(mxv, __shfl_xor_sync(0xffffffffu, mxv, o));
        float sm = 0.f;
        for (int t = ln; t < 1024; t += 32) {
            float e = expf(p[r*1024+t] - mxv);
            p[r*1024+t] = e;
            sm += e;
        }
        #pragma unroll
        for (int o = 16; o; o >>= 1) sm += __shfl_xor_sync(0xffffffffu, sm, o);
        if (ln == 0) rinv[r] = 1.f/sm;
    }
    __syncthreads();
    int c2 = tid&63, hf = tid>>6;
    float2 acc2[8];
    #pragma unroll
    for (int r = 0; r < 8; r++) acc2[r] = make_float2(0.f, 0.f);
    for (int t = hf*256; t < hf*256+256; t++) {
        float2 vv = *(const float2*)&g_v[t*128 + 2*c2];
        #pragma unroll
        for (int r = 0; r < 8; r++) {
            float pv = p[r*1024+t];
            acc2[r] = ffma2(make_float2(pv, pv), vv, acc2[r]);
        }
    }
    __syncthreads();
    float2* pbuf = (float2*)p;
    if (hf) {
        #pragma unroll
        for (int r = 0; r < 8; r++) pbuf[(hf-1)*512 + r*64 + c2] = acc2[r];
    }
    __syncthreads();
    if (hf == 0) {
        #pragma unroll
        for (int r = 0; r < 8; r++) {
            float2 sv = acc2[r];
            #pragma unroll
            for (int q = 0; q < 3; q++) {
                float2 o = pbuf[q*512 + r*64 + c2];
                sv.x += o.x; sv.y += o.y;
            }
            g_ao[(r0+r)*128 + 2*c2]     = sv.x*rinv[r];
            g_ao[(r0+r)*128 + 2*c2 + 1] = sv.y*rinv[r];
        }
    }
}

__global__ void __launch_bounds__(256) k_cs1() {
    __shared__ float red[128];
    int s0 = blockIdx.x*16, tid = threadIdx.x;
    int c = tid&127, sy = tid>>7;
    float ss = 0.f;
    for (int s = sy; s < 16; s += 2) { float v = g_ao[(s0+s)*128+c]; ss += v*v; }
    if (sy) red[c] = ss;
    __syncthreads();
    if (!sy) atomicAdd(&g_css[c], ss + red[c]);
}

__global__ void __launch_bounds__(256) k_cs2() {
    __shared__ float red[128];
    int s0 = blockIdx.x*16, tid = threadIdx.x;
    int c = tid&127, sy = tid>>7;
    float inv1 = 1.f/fmaxf(sqrtf(g_css[c]), 1e-12f);
    float ss = 0.f;
    for (int s = sy; s < 16; s += 2) {
        float v = g_ao[(s0+s)*128+c]*inv1 + g_e[(s0+s)*128+c];
        g_o2[(s0+s)*128+c] = v;
        ss += v*v;
    }
    if (sy) red[c] = ss;
    __syncthreads();
    if (!sy) atomicAdd(&g_css2[c], ss + red[c]);
}

__global__ void __launch_bounds__(128) k_cs3r() {
    __shared__ float red[4];
    int s = blockIdx.x, d = threadIdx.x;
    int wrp = d>>5, ln = d&31;
    float inv2 = 1.f/fmaxf(sqrtf(g_css2[d]), 1e-12f);
    float v = g_o2[s*128+d]*inv2;
    g_ea[s*128+d] = v;
    float ss = v*v;
    #pragma unroll
    for (int o = 16; o; o >>= 1) ss += __shfl_xor_sync(0xffffffffu, ss, o);
    if (ln == 0) red[wrp] = ss;
    __syncthreads();
    if (d == 0) g_sq[s] = red[0]+red[1]+red[2]+red[3];
}

__global__ void k_gram(float* __restrict__ dout) {
    __shared__ float ea_i[32][129];
    __shared__ float ea_j[32][129];
    __shared__ float sqi[32], sqj[32];
    __shared__ float rmax[8];
    int i0 = blockIdx.y*32, j0 = blockIdx.x*32;
    int tid = threadIdx.x;
    for (int idx = tid; idx < 4096; idx += 256) {
        int r = idx>>7, d = idx&127;
        ea_i[r][d] = g_ea[(i0+r)*128+d];
        ea_j[r][d] = g_ea[(j0+r)*128+d];
    }
    if (tid < 32) { sqi[tid] = g_sq[i0+tid]; sqj[tid] = g_sq[j0+tid]; }
    __syncthreads();
    int tx = tid&15, ty = tid>>4;
    int r0 = 2*ty, c0 = 2*tx;
    float d00 = 0.f, d01 = 0.f, d10 = 0.f, d11 = 0.f;
    #pragma unroll 4
    for (int d = 0; d < 128; d++) {
        float a0 = ea_i[r0][d], a1 = ea_i[r0+1][d];
        float b0 = ea_j[c0][d], b1 = ea_j[c0+1][d];
        d00 += a0*b0; d01 += a0*b1; d10 += a1*b0; d11 += a1*b1;
    }
    float lm = 0.f;
    float dots[4] = {d00, d01, d10, d11};
    #pragma unroll
    for (int u = 0; u < 4; u++) {
        int r = r0 + (u>>1), c = c0 + (u&1);
        float d2 = fmaxf(sqi[r] + sqj[c] - 2.f*dots[u], 0.f);
        float dd = sqrtf(d2 + 1e-12f);
        dout[(i0+r)*1024 + j0 + c] = dd;
        lm = fmaxf(lm, dd);
    }
    #pragma unroll
    for (int o = 16; o; o >>= 1) lm = fmaxf(lm, __shfl_xor_sync(0xffffffffu, lm, o));
    if ((tid&31) == 0) rmax[tid>>5] = lm;
    __syncthreads();
    if (tid == 0) {
        float m = 0.f;
        for (int i = 0; i < 8; i++) m = fmaxf(m, rmax[i]);
        atomicMax(&g_dmax, __float_as_uint(m));
    }
}

__global__ void k_final(float* __restrict__ dout) {
    float inv = 1.f/__uint_as_float(g_dmax);
    int i = blockIdx.x*256 + threadIdx.x;
    dout[i] = 1.f - dout[i]*inv;
}

extern "C" void kernel_launch(void* const* d_in, const int* in_sizes, int n_in,
                              void* d_out, int out_size) {
    const float* x   = (const float*)d_in[0];
    const float* c1w = (const float*)d_in[1];
    const float* c1b = (const float*)d_in[2];
    const float* g1g = (const float*)d_in[3];
    const float* g1b = (const float*)d_in[4];
    const float* c2w = (const float*)d_in[5];
    const float* c2b = (const float*)d_in[6];
    const float* g2g = (const float*)d_in[7];
    const float* g2b = (const float*)d_in[8];
    const float* c3w = (const float*)d_in[9];
    const float* c3b = (const float*)d_in[10];
    const float* g3g = (const float*)d_in[11];
    const float* g3b = (const float*)d_in[12];
    const float* fcw = (const float*)d_in[13];
    const float* fcb = (const float*)d_in[14];
    const float* wq  = (const float*)d_in[15];
    const float* bq  = (const float*)d_in[16];
    const float* wk  = (const float*)d_in[17];
    const float* bk  = (const float*)d_in[18];
    const float* wv  = (const float*)d_in[19];
    const float* bv  = (const float*)d_in[20];
    float* out = (float*)d_out;

    cudaFuncSetAttribute(k_conv2mma, cudaFuncAttributeMaxDynamicSharedMemorySize, C2_SMEM);
    cudaFuncSetAttribute(k_conv3mma4, cudaFuncAttributeMaxDynamicSharedMemorySize, C3_SMEM);

    k_zero<<<1, 256>>>();
    k_prep<<<768, 256>>>(c2w, c3w);
    k_conv1<<<1024, 256>>>(x, c1w, c1b, g1g, g1b);
    k_conv2mma<<<dim3(1024,2), 384, C2_SMEM>>>(c2b, g2g, g2b);
    k_conv3mma4<<<256, 512, C3_SMEM>>>(c3b, g3g, g3b);
    k_fc  <<<128, 256>>>(fcw, fcb);
    k_qkv <<<128, 256>>>(wq, bq, wk, bk, wv, bv);
    k_attn<<<128, 256>>>();
    k_cs1 <<<64, 256>>>();
    k_cs2 <<<64, 256>>>();
    k_cs3r<<<1024, 128>>>();
    k_gram<<<dim3(32,32), 256>>>(out);
    k_final<<<4096, 256>>>(out);
}

// round 16
// speedup vs baseline: 1.1625x; 1.0741x over previous
#include <cuda_runtime.h>
#include <math.h>

#define NS 1024

__device__ float g_h1p[NS*32*36*16];
__device__ float g_h2p[NS*64*12*4];
__device__ float g_h3p[NS*128*4*2];
__device__ float g_w2t[4*192*64];
__device__ float g_w3t[16*96*128];
__device__ float g_e [NS*128];
__device__ float g_q [NS*128];
__device__ float g_k [NS*128];
__device__ float g_v [NS*128];
__device__ float g_ao[NS*128];
__device__ float g_o2[NS*128];
__device__ float g_ea[NS*128];
__device__ float g_sq[NS];
__device__ float g_css[128];
__device__ float g_css2[128];
__device__ unsigned int g_dmax;

__device__ __forceinline__ float selu_f(float x) {
    const float a = 1.6732632423543772f, sc = 1.0507009873554805f;
    return x > 0.f ? sc * x : sc * a * (expf(x) - 1.f);
}

__device__ __forceinline__ float2 ffma2(float2 a, float2 b, float2 c) {
    unsigned long long ua = *(unsigned long long*)&a;
    unsigned long long ub = *(unsigned long long*)&b;
    unsigned long long uc = *(unsigned long long*)&c;
    unsigned long long ud;
    asm("fma.rn.f32x2 %0, %1, %2, %3;" : "=l"(ud) : "l"(ua), "l"(ub), "l"(uc));
    return *(float2*)&ud;
}

__device__ __forceinline__ unsigned tf32c(float x) {
    unsigned u; asm("cvt.rna.tf32.f32 %0, %1;" : "=r"(u) : "f"(x)); return u;
}
__device__ __forceinline__ float tf32f(float x) {
    return __uint_as_float(tf32c(x));
}
__device__ __forceinline__ void mma_tf32(float* d, const unsigned* a, const unsigned* b) {
    asm volatile("mma.sync.aligned.m16n8k8.row.col.f32.tf32.tf32.f32 "
        "{%0,%1,%2,%3}, {%4,%5,%6,%7}, {%8,%9}, {%0,%1,%2,%3};"
        : "+f"(d[0]), "+f"(d[1]), "+f"(d[2]), "+f"(d[3])
        : "r"(a[0]), "r"(a[1]), "r"(a[2]), "r"(a[3]), "r"(b[0]), "r"(b[1]));
}

__device__ __forceinline__ unsigned s2u(const void* p) {
    return (unsigned)__cvta_generic_to_shared(p);
}
template<int IMM>
__device__ __forceinline__ unsigned lds1(unsigned a) {
    unsigned v;
    asm volatile("ld.shared.b32 %0, [%1+%2];" : "=r"(v) : "r"(a), "n"(IMM));
    return v;
}
__device__ __forceinline__ void cpa4(void* dst, const void* src, int sz) {
    asm volatile("cp.async.ca.shared.global [%0], [%1], 4, %2;"
                 :: "r"(s2u(dst)), "l"(src), "r"(sz));
}
__device__ __forceinline__ void cpa16(void* dst, const void* src) {
    asm volatile("cp.async.cg.shared.global [%0], [%1], 16;"
                 :: "r"(s2u(dst)), "l"(src));
}
__device__ __forceinline__ void cpa_commit() { asm volatile("cp.async.commit_group;"); }
template<int N> __device__ __forceinline__ void cpa_wait() {
    asm volatile("cp.async.wait_group %0;" :: "n"(N));
}

__global__ void k_zero() {
    int t = threadIdx.x;
    if (t < 128) { g_css[t] = 0.f; g_css2[t] = 0.f; }
    if (t == 255) g_dmax = 0u;
}

__global__ void __launch_bounds__(256) k_prep(const float* __restrict__ w2,
        const float* __restrict__ w3) {
    int i = blockIdx.x*256 + threadIdx.x;
    if (i < 49152)  g_w2t[i] = tf32f(w2[(i&63)*768 + (i>>6)]);
    if (i < 196608) g_w3t[i] = tf32f(w3[(i&127)*1536 + (i>>7)]);
}

// ===== conv1 =====
__global__ void __launch_bounds__(256) k_conv1(const float* __restrict__ x,
        const float* __restrict__ w, const float* __restrict__ bias,
        const float* __restrict__ gg, const float* __restrict__ gb) {
    __shared__ __align__(16) float pad[77*68];
    int s = blockIdx.x, tid = threadIdx.x, lane = tid & 31;
    const float* xs = x + s*4608;
    for (int i = tid; i < 77*68; i += 256) {
        int r = i/68, cc = i - r*68;
        int ih = r-2, iw = cc-1;
        pad[i] = (ih>=0 && ih<72 && iw>=0 && iw<64) ? xs[ih*64+iw] : 0.f;
    }
    __syncthreads();
    for (int cc4 = 0; cc4 < 4; cc4++) {
        int ch = cc4*8 + (tid>>5);
        float2 w2[24];
        #pragma unroll
        for (int k2 = 0; k2 < 24; k2++) { float wv = w[ch*24+k2]; w2[k2] = make_float2(wv, wv); }
        float bi = bias[ch];
        float pm[18], pn[18], sum = 0.f, sq = 0.f;
        for (int wi = 0; wi < 18; wi++) {
            int wdw = wi*32 + lane;
            int ph = wdw>>4, pw = wdw&15;
            float2 acc[2][2];
            #pragma unroll
            for (int r = 0; r < 2; r++)
                #pragma unroll
                for (int cp = 0; cp < 2; cp++) acc[r][cp] = make_float2(bi, bi);
            #pragma unroll
            for (int ir = 0; ir < 7; ir++) {
                const float* pr = &pad[(2*ph+ir)*68 + 4*pw];
                float4 va = *(const float4*)pr;
                float4 vb = *(const float4*)(pr + 4);
                float v[7] = {va.x, va.y, va.z, va.w, vb.x, vb.y, vb.z};
                #pragma unroll
                for (int r = 0; r < 2; r++) {
                    int kh = ir - r;
                    if (kh >= 0 && kh < 6) {
                        #pragma unroll
                        for (int kw = 0; kw < 4; kw++) {
                            float2 wv = w2[kh*4+kw];
                            #pragma unroll
                            for (int cp = 0; cp < 2; cp++)
                                acc[r][cp] = ffma2(make_float2(v[2*cp+kw], v[2*cp+kw+1]), wv, acc[r][cp]);
                        }
                    }
                }
            }
            float mx = -1e30f, mn = 1e30f;
            #pragma unroll
            for (int r = 0; r < 2; r++)
                #pragma unroll
                for (int cp = 0; cp < 2; cp++) {
                    float u0 = selu_f(acc[r][cp].x), u1 = selu_f(acc[r][cp].y);
                    sum += u0+u1; sq += u0*u0+u1*u1;
                    mx = fmaxf(mx, fmaxf(u0,u1)); mn = fminf(mn, fminf(u0,u1));
                }
            pm[wi] = mx; pn[wi] = mn;
        }
        #pragma unroll
        for (int o = 16; o; o >>= 1) {
            sum += __shfl_xor_sync(0xffffffffu, sum, o);
            sq  += __shfl_xor_sync(0xffffffffu, sq , o);
        }
        float mean = sum*(1.f/4608.f);
        float var  = sq*(1.f/4608.f) - mean*mean;
        float sc = gg[ch]*rsqrtf(var+1e-5f);
        float sh = gb[ch] - mean*sc;
        for (int wi = 0; wi < 18; wi++) {
            int wdw = wi*32 + lane;
            int ph = wdw>>4, pw = wdw&15;
            float val = sc>0.f ? pm[wi]*sc+sh : pn[wi]*sc+sh;
            g_h1p[((s*32+ch)*36+ph)*16+pw] = tf32f(val);
        }
    }
}

// ===== conv2: TF32 mma, cp.async double-buffered, strength-reduced LDS addressing =====
#define C2_STG 13144
#define C2_SMEM (2*C2_STG*4)
#define C2_STEP(U) { \
    unsigned A[4]; \
    A[0] = lds1<(288*(U))*4>(wp); \
    A[1] = lds1<(288*(U)+8)*4>(wp); \
    A[2] = lds1<(288*(U)+144)*4>(wp); \
    A[3] = lds1<(288*(U)+152)*4>(wp); \
    _Pragma("unroll") \
    for (int j = 0; j < 12; j++) { \
        unsigned B[2]; \
        B[0] = lds1<(38*(U))*4>(bp[j]); \
        B[1] = lds1<(38*(U)+19)*4>(bp[j]); \
        mma_tf32(cfr[j], A, B); \
    } }
__global__ void __launch_bounds__(384, 2) k_conv2mma(const float* __restrict__ bias,
        const float* __restrict__ gg, const float* __restrict__ gb) {
    extern __shared__ float dsm[];
    float* cv = dsm;
    int s = blockIdx.x, ocb = 32*blockIdx.y;
    int tid = threadIdx.x, wrp = tid>>5, t = tid&31;
    int m = wrp & 1, ng = wrp >> 1;
    float cfr[12][4];
    #pragma unroll
    for (int j = 0; j < 12; j++) { cfr[j][0]=cfr[j][1]=cfr[j][2]=cfr[j][3]=0.f; }
    int off[12];
    #pragma unroll
    for (int j = 0; j < 12; j++) {
        int n = ng*96 + j*8 + (t>>2);
        off[j] = (n>>4)*19 + (n&15);
    }
    auto stage = [&](int ck, float* buf) {
        float* wsb = buf;
        float* padb = buf + 6912;
        #pragma unroll
        for (int u = 0; u < 16; u++) {
            int i = tid + u*384;
            cpa4(&wsb[(i>>5)*36 + (i&31)],
                 &g_w2t[ck*12288 + (i>>5)*64 + ocb + (i&31)], 4);
        }
        for (int i = tid; i < 6232; i += 384) {
            int icl = i/779, rem = i - icl*779;
            int row = rem/19, col = rem - row*19;
            int ih = row - 2, iw = col - 1;
            bool ok = (ih>=0 && ih<36 && iw>=0 && iw<16);
            cpa4(&padb[i],
                 &g_h1p[((s*32 + ck*8 + icl)*36 + (ok?ih:0))*16 + (ok?iw:0)],
                 ok ? 4 : 0);
        }
        cpa_commit();
    };
    stage(0, dsm);
    for (int ck = 0; ck < 4; ck++) {
        if (ck > 0) __syncthreads();
        if (ck < 3) stage(ck+1, dsm + ((ck+1)&1)*C2_STG);
        if (ck < 3) cpa_wait<1>(); else cpa_wait<0>();
        __syncthreads();
        unsigned wsb = s2u(dsm + (ck&1)*C2_STG);
        unsigned wp = wsb + ((t&3)*36 + m*16 + (t>>2))*4;
        unsigned bp[12];
        #pragma unroll
        for (int j = 0; j < 12; j++) bp[j] = wsb + 6912*4 + ((t&3) + off[j])*4;
        #pragma unroll 1
        for (int icl = 0; icl < 8; icl++) {
            C2_STEP(0)
            C2_STEP(1)
            C2_STEP(2)
            wp += 864*4;
            #pragma unroll
            for (int j = 0; j < 12; j++) bp[j] += 779*4;
        }
    }
    __syncthreads();
    int ocl = m*16 + (t>>2);
    float b0v = bias[ocb+ocl], b8v = bias[ocb+ocl+8];
    #pragma unroll
    for (int j = 0; j < 12; j++) {
        int n0 = ng*96 + j*8 + (t&3)*2;
        cv[ocl*577 + n0]     = selu_f(cfr[j][0] + b0v);
        cv[ocl*577 + n0 + 1] = selu_f(cfr[j][1] + b0v);
        cv[(ocl+8)*577 + n0]     = selu_f(cfr[j][2] + b8v);
        cv[(ocl+8)*577 + n0 + 1] = selu_f(cfr[j][3] + b8v);
    }
    __syncthreads();
    if (tid < 256) {
        int g = tid>>4, e = tid&15;
        float sm = 0.f, sq = 0.f;
        #pragma unroll
        for (int cl = 0; cl < 2; cl++)
            for (int i = e; i < 576; i += 16) {
                float v = cv[(2*g+cl)*577 + i];
                sm += v; sq += v*v;
            }
        #pragma unroll
        for (int o = 8; o; o >>= 1) {
            sm += __shfl_xor_sync(0xffffffffu, sm, o);
            sq += __shfl_xor_sync(0xffffffffu, sq, o);
        }
        float mean = sm*(1.f/1152.f);
        float var  = sq*(1.f/1152.f) - mean*mean;
        float inv  = rsqrtf(var + 1e-5f);
        #pragma unroll
        for (int ii = 0; ii < 6; ii++) {
            int u = e + 16*ii;
            int cl = u/48, rem = u - cl*48;
            int ph = rem>>2, pw = rem&3;
            float scv = gg[ocb+2*g+cl]*inv;
            float shv = gb[ocb+2*g+cl] - mean*scv;
            float mx = -1e30f;
            #pragma unroll
            for (int r = 0; r < 3; r++)
                #pragma unroll
                for (int c = 0; c < 4; c++)
                    mx = fmaxf(mx, cv[(2*g+cl)*577 + (3*ph+r)*16 + 4*pw+c]*scv + shv);
            g_h2p[((s*64 + ocb + 2*g + cl)*12 + ph)*4 + pw] = tf32f(mx);
        }
    }
}

// ===== conv3: TF32 mma, 4 frames/block, cp.async double-buffered, SR addressing =====
#define C3_STG 14576
#define C3_SMEM (2*C3_STG*4)
#define C3_STEP(U) { \
    unsigned A[4]; \
    A[0] = lds1<(1056*(U))*4>(wp); \
    A[1] = lds1<(1056*(U)+8)*4>(wp); \
    A[2] = lds1<(1056*(U)+528)*4>(wp); \
    A[3] = lds1<(1056*(U)+536)*4>(wp); \
    _Pragma("unroll") \
    for (int j = 0; j < 12; j++) { \
        unsigned B[2]; \
        B[0] = lds1<(14*(U))*4>(bp[j]); \
        B[1] = lds1<(14*(U)+7)*4>(bp[j]); \
        mma_tf32(cfr[j], A, B); \
    } }
__global__ void __launch_bounds__(512) k_conv3mma4(const float* __restrict__ bias,
        const float* __restrict__ gg, const float* __restrict__ gb) {
    extern __shared__ float dsm3[];
    float* cv = dsm3;
    int s4 = blockIdx.x*4, tid = threadIdx.x, wrp = tid>>5, t = tid&31;
    int m = wrp & 7, ng = wrp >> 3;
    float cfr[12][4];
    #pragma unroll
    for (int j = 0; j < 12; j++) { cfr[j][0]=cfr[j][1]=cfr[j][2]=cfr[j][3]=0.f; }
    int off[12];
    #pragma unroll
    for (int j = 0; j < 12; j++) {
        int n = ng*96 + j*8 + (t>>2);
        int f = (ng*96 + j*8)/48;
        int np = n - 48*f;
        off[j] = f*476 + (np>>2)*7 + (np&3);
    }
    auto stage = [&](int ck, float* buf) {
        float* wsb = buf;
        float* padb = buf + 12672;
        #pragma unroll
        for (int u = 0; u < 6; u++) {
            int i = (tid + u*512)*4;
            cpa16(&wsb[(i>>7)*132 + (i&127)], &g_w3t[ck*12288 + i]);
        }
        for (int i = tid; i < 1904; i += 512) {
            int f = i/476, rem = i - f*476;
            int icl = rem/119, rem2 = rem - icl*119;
            int rr = rem2/7, cc = rem2 - rr*7;
            int ih = rr-2, iw = cc-1;
            bool ok = (ih>=0 && ih<12 && iw>=0 && iw<4);
            cpa4(&padb[i],
                 &g_h2p[(((s4+f)*64 + ck*4 + icl)*12 + (ok?ih:0))*4 + (ok?iw:0)],
                 ok ? 4 : 0);
        }
        cpa_commit();
    };
    stage(0, dsm3);
    for (int ck = 0; ck < 16; ck++) {
        if (ck > 0) __syncthreads();
        if (ck < 15) stage(ck+1, dsm3 + ((ck+1)&1)*C3_STG);
        if (ck < 15) cpa_wait<1>(); else cpa_wait<0>();
        __syncthreads();
        unsigned wsb = s2u(dsm3 + (ck&1)*C3_STG);
        unsigned wp = wsb + ((t&3)*132 + m*16 + (t>>2))*4;
        unsigned bp[12];
        #pragma unroll
        for (int j = 0; j < 12; j++) bp[j] = wsb + 12672*4 + ((t&3) + off[j])*4;
        #pragma unroll 1
        for (int icl = 0; icl < 4; icl++) {
            C3_STEP(0)
            C3_STEP(1)
            C3_STEP(2)
            wp += 3168*4;
            #pragma unroll
            for (int j = 0; j < 12; j++) bp[j] += 119*4;
        }
    }
    int oc0 = m*16 + (t>>2);
    float b0v = bias[oc0], b8v = bias[oc0+8];
    for (int f = 0; f < 4; f++) {
        __syncthreads();
        #pragma unroll
        for (int j = 0; j < 12; j++) {
            int fj = ng*2 + j/6;
            if (fj == f) {
                int np = (j - (j/6)*6)*8 + (t&3)*2;
                cv[oc0*49 + np]     = selu_f(cfr[j][0] + b0v);
                cv[oc0*49 + np + 1] = selu_f(cfr[j][1] + b0v);
                cv[(oc0+8)*49 + np]     = selu_f(cfr[j][2] + b8v);
                cv[(oc0+8)*49 + np + 1] = selu_f(cfr[j][3] + b8v);
            }
        }
        __syncthreads();
        int g = tid>>4, e = tid&15;
        float sm = 0.f, sq = 0.f;
        #pragma unroll
        for (int cl = 0; cl < 4; cl++)
            for (int i = e; i < 48; i += 16) {
                float v = cv[(4*g+cl)*49 + i];
                sm += v; sq += v*v;
            }
        #pragma unroll
        for (int o = 8; o; o >>= 1) {
            sm += __shfl_xor_sync(0xffffffffu, sm, o);
            sq += __shfl_xor_sync(0xffffffffu, sq, o);
        }
        float mean = sm*(1.f/192.f);
        float var  = sq*(1.f/192.f) - mean*mean;
        float inv  = rsqrtf(var + 1e-5f);
        #pragma unroll
        for (int ii = 0; ii < 2; ii++) {
            int u = e + 16*ii;
            int cl = u>>3, rem = u&7;
            int ph = rem>>1, pw = rem&1;
            float scv = gg[4*g+cl]*inv;
            float shv = gb[4*g+cl] - mean*scv;
            float mx = -1e30f;
            #pragma unroll
            for (int r = 0; r < 3; r++)
                #pragma unroll
                for (int c = 0; c < 2; c++)
                    mx = fmaxf(mx, cv[(4*g+cl)*49 + (3*ph+r)*4 + 2*pw+c]*scv + shv);
            g_h3p[(((s4+f)*128 + 4*g + cl)*4 + ph)*2 + pw] = mx;
        }
    }
}

// ===== fc =====
__global__ void __launch_bounds__(256) k_fc(const float* __restrict__ w,
        const float* __restrict__ bias) {
    __shared__ float xs[8*65];
    __shared__ float wt[64*129];
    __shared__ float sred[8][4];
    int r0 = blockIdx.x*8, tid = threadIdx.x;
    int c = tid&127, rg = tid>>7, wrp = tid>>5, ln = tid&31;
    float acc[4];
    float b0 = bias[c];
    #pragma unroll
    for (int rr = 0; rr < 4; rr++) acc[rr] = b0;
    for (int k0 = 0; k0 < 1024; k0 += 64) {
        __syncthreads();
        for (int i = tid; i < 512; i += 256) {
            int r = i>>6, kk = i&63;
            xs[r*65+kk] = g_h3p[(r0+r)*1024 + k0 + kk];
        }
        for (int i = tid; i < 8192; i += 256) {
            int j = i>>6, kk = i&63;
            wt[kk*129+j] = w[j*1024 + k0 + kk];
        }
        __syncthreads();
        for (int kk = 0; kk < 64; kk++) {
            float wv = wt[kk*129+c];
            #pragma unroll
            for (int rr = 0; rr < 4; rr++) acc[rr] += xs[(rg*4+rr)*65+kk]*wv;
        }
    }
    float v[4];
    #pragma unroll
    for (int rr = 0; rr < 4; rr++) v[rr] = selu_f(acc[rr]);
    #pragma unroll
    for (int rr = 0; rr < 4; rr++) {
        float ss = v[rr]*v[rr];
        #pragma unroll
        for (int o = 16; o; o >>= 1) ss += __shfl_xor_sync(0xffffffffu, ss, o);
        if (ln == 0) sred[wrp][rr] = ss;
    }
    __syncthreads();
    #pragma unroll
    for (int rr = 0; rr < 4; rr++) {
        float t = sred[rg*4+0][rr] + sred[rg*4+1][rr] + sred[rg*4+2][rr] + sred[rg*4+3][rr];
        float n = fmaxf(sqrtf(t), 1e-12f);
        g_e[(r0+rg*4+rr)*128 + c] = v[rr]/n;
    }
}

// ===== qkv =====
__global__ void __launch_bounds__(256) k_qkv(const float* __restrict__ wq,
        const float* __restrict__ bq, const float* __restrict__ wk,
        const float* __restrict__ bk, const float* __restrict__ wv,
        const float* __restrict__ bv) {
    __shared__ float es[8*132];
    __shared__ float wt[64*129];
    int r0 = blockIdx.x*8, tid = threadIdx.x;
    int c = tid&127, rg = tid>>7;
    for (int i = tid; i < 1024; i += 256) {
        int r = i>>7, d = i&127;
        es[r*132+d] = g_e[(r0+r)*128 + d];
    }
    const float* W[3] = {wq, wk, wv};
    const float* B[3] = {bq, bk, bv};
    float* O[3] = {g_q, g_k, g_v};
    for (int m = 0; m < 3; m++) {
        float acc[4];
        float b0 = B[m][c];
        #pragma unroll
        for (int rr = 0; rr < 4; rr++) acc[rr] = b0;
        for (int k0 = 0; k0 < 128; k0 += 64) {
            __syncthreads();
            for (int i = tid; i < 8192; i += 256) {
                int j = i>>6, kk = i&63;
                wt[kk*129+j] = W[m][j*128 + k0 + kk];
            }
            __syncthreads();
            for (int kk = 0; kk < 64; kk++) {
                float wvv = wt[kk*129+c];
                #pragma unroll
                for (int rr = 0; rr < 4; rr++) acc[rr] += es[(rg*4+rr)*132 + k0 + kk]*wvv;
            }
        }
        #pragma unroll
        for (int rr = 0; rr < 4; rr++) {
            int sr = r0 + rg*4 + rr;
            float u = selu_f(acc[rr]);
            if (m == 1) {
                float f = expf((float)(c & ~1) * (-9.210340371976184f/128.f));
                float ang = (float)sr * f;
                u += (c & 1) ? cosf(ang) : sinf(ang);
            }
            O[m][sr*128 + c] = u;
        }
    }
}

// ===== attn =====
__global__ void __launch_bounds__(256) k_attn() {
    __shared__ __align__(16) float q8[8*132];
    __shared__ __align__(16) float p[8*1024];
    __shared__ float rinv[8];
    int r0 = blockIdx.x*8, tid = threadIdx.x;
    for (int i = tid; i < 1024; i += 256) {
        int r = i>>7, d = i&127;
        q8[r*132+d] = g_q[(r0+r)*128 + d];
    }
    __syncthreads();
    const float scale = 0.08838834764831845f;
    for (int t = tid; t < 1024; t += 256) {
        float2 a2[8];
        #pragma unroll
        for (int r = 0; r < 8; r++) a2[r] = make_float2(0.f, 0.f);
        const float4* kr = (const float4*)(g_k + t*128);
        #pragma unroll 4
        for (int d4 = 0; d4 < 32; d4++) {
            float4 kv = kr[d4];
            float2 klo = make_float2(kv.x, kv.y), khi = make_float2(kv.z, kv.w);
            #pragma unroll
            for (int r = 0; r < 8; r++) {
                float4 qv = *(const float4*)&q8[r*132 + d4*4];
                a2[r] = ffma2(make_float2(qv.x, qv.y), klo, a2[r]);
                a2[r] = ffma2(make_float2(qv.z, qv.w), khi, a2[r]);
            }
        }
        #pragma unroll
        for (int r = 0; r < 8; r++) p[r*1024+t] = (a2[r].x + a2[r].y)*scale;
    }
    __syncthreads();
    int wrp = tid>>5, ln = tid&31;
    {
        int r = wrp;
        float mxv = -1e30f;
        for (int t = ln; t < 1024; t += 32) mxv = fmaxf(mxv, p[r*1024+t]);
        #pragma unroll
        for (int o = 16; o; o >>= 1) mxv = fmaxf(mxv, __shfl_xor_sync(0xffffffffu, mxv, o));
        float sm = 0.f;
        for (int t = ln; t < 1024; t += 32) {
            float e = expf(p[r*1024+t] - mxv);
            p[r*1024+t] = e;
            sm += e;
        }
        #pragma unroll
        for (int o = 16; o; o >>= 1) sm += __shfl_xor_sync(0xffffffffu, sm, o);
        if (ln == 0) rinv[r] = 1.f/sm;
    }
    __syncthreads();
    int c2 = tid&63, hf = tid>>6;
    float2 acc2[8];
    #pragma unroll
    for (int r = 0; r < 8; r++) acc2[r] = make_float2(0.f, 0.f);
    for (int t = hf*256; t < hf*256+256; t++) {
        float2 vv = *(const float2*)&g_v[t*128 + 2*c2];
        #pragma unroll
        for (int r = 0; r < 8; r++) {
            float pv = p[r*1024+t];
            acc2[r] = ffma2(make_float2(pv, pv), vv, acc2[r]);
        }
    }
    __syncthreads();
    float2* pbuf = (float2*)p;
    if (hf) {
        #pragma unroll
        for (int r = 0; r < 8; r++) pbuf[(hf-1)*512 + r*64 + c2] = acc2[r];
    }
    __syncthreads();
    if (hf == 0) {
        #pragma unroll
        for (int r = 0; r < 8; r++) {
            float2 sv = acc2[r];
            #pragma unroll
            for (int q = 0; q < 3; q++) {
                float2 o = pbuf[q*512 + r*64 + c2];
                sv.x += o.x; sv.y += o.y;
            }
            g_ao[(r0+r)*128 + 2*c2]     = sv.x*rinv[r];
            g_ao[(r0+r)*128 + 2*c2 + 1] = sv.y*rinv[r];
        }
    }
}

__global__ void __launch_bounds__(256) k_cs1() {
    __shared__ float red[128];
    int s0 = blockIdx.x*16, tid = threadIdx.x;
    int c = tid&127, sy = tid>>7;
    float ss = 0.f;
    for (int s = sy; s < 16; s += 2) { float v = g_ao[(s0+s)*128+c]; ss += v*v; }
    if (sy) red[c] = ss;
    __syncthreads();
    if (!sy) atomicAdd(&g_css[c], ss + red[c]);
}

__global__ void __launch_bounds__(256) k_cs2() {
    __shared__ float red[128];
    int s0 = blockIdx.x*16, tid = threadIdx.x;
    int c = tid&127, sy = tid>>7;
    float inv1 = 1.f/fmaxf(sqrtf(g_css[c]), 1e-12f);
    float ss = 0.f;
    for (int s = sy; s < 16; s += 2) {
        float v = g_ao[(s0+s)*128+c]*inv1 + g_e[(s0+s)*128+c];
        g_o2[(s0+s)*128+c] = v;
        ss += v*v;
    }
    if (sy) red[c] = ss;
    __syncthreads();
    if (!sy) atomicAdd(&g_css2[c], ss + red[c]);
}

__global__ void __launch_bounds__(128) k_cs3r() {
    __shared__ float red[4];
    int s = blockIdx.x, d = threadIdx.x;
    int wrp = d>>5, ln = d&31;
    float inv2 = 1.f/fmaxf(sqrtf(g_css2[d]), 1e-12f);
    float v = g_o2[s*128+d]*inv2;
    g_ea[s*128+d] = v;
    float ss = v*v;
    #pragma unroll
    for (int o = 16; o; o >>= 1) ss += __shfl_xor_sync(0xffffffffu, ss, o);
    if (ln == 0) red[wrp] = ss;
    __syncthreads();
    if (d == 0) g_sq[s] = red[0]+red[1]+red[2]+red[3];
}

__global__ void k_gram(float* __restrict__ dout) {
    __shared__ float ea_i[32][129];
    __shared__ float ea_j[32][129];
    __shared__ float sqi[32], sqj[32];
    __shared__ float rmax[8];
    int i0 = blockIdx.y*32, j0 = blockIdx.x*32;
    int tid = threadIdx.x;
    for (int idx = tid; idx < 4096; idx += 256) {
        int r = idx>>7, d = idx&127;
        ea_i[r][d] = g_ea[(i0+r)*128+d];
        ea_j[r][d] = g_ea[(j0+r)*128+d];
    }
    if (tid < 32) { sqi[tid] = g_sq[i0+tid]; sqj[tid] = g_sq[j0+tid]; }
    __syncthreads();
    int tx = tid&15, ty = tid>>4;
    int r0 = 2*ty, c0 = 2*tx;
    float d00 = 0.f, d01 = 0.f, d10 = 0.f, d11 = 0.f;
    #pragma unroll 4
    for (int d = 0; d < 128; d++) {
        float a0 = ea_i[r0][d], a1 = ea_i[r0+1][d];
        float b0 = ea_j[c0][d], b1 = ea_j[c0+1][d];
        d00 += a0*b0; d01 += a0*b1; d10 += a1*b0; d11 += a1*b1;
    }
    float lm = 0.f;
    float dots[4] = {d00, d01, d10, d11};
    #pragma unroll
    for (int u = 0; u < 4; u++) {
        int r = r0 + (u>>1), c = c0 + (u&1);
        float d2 = fmaxf(sqi[r] + sqj[c] - 2.f*dots[u], 0.f);
        float dd = sqrtf(d2 + 1e-12f);
        dout[(i0+r)*1024 + j0 + c] = dd;
        lm = fmaxf(lm, dd);
    }
    #pragma unroll
    for (int o = 16; o; o >>= 1) lm = fmaxf(lm, __shfl_xor_sync(0xffffffffu, lm, o));
    if ((tid&31) == 0) rmax[tid>>5] = lm;
    __syncthreads();
    if (tid == 0) {
        float m = 0.f;
        for (int i = 0; i < 8; i++) m = fmaxf(m, rmax[i]);
        atomicMax(&g_dmax, __float_as_uint(m));
    }
}

__global__ void k_final(float* __restrict__ dout) {
    float inv = 1.f/__uint_as_float(g_dmax);
    int i = blockIdx.x*256 + threadIdx.x;
    dout[i] = 1.f - dout[i]*inv;
}

extern "C" void kernel_launch(void* const* d_in, const int* in_sizes, int n_in,
                              void* d_out, int out_size) {
    const float* x   = (const float*)d_in[0];
    const float* c1w = (const float*)d_in[1];
    const float* c1b = (const float*)d_in[2];
    const float* g1g = (const float*)d_in[3];
    const float* g1b = (const float*)d_in[4];
    const float* c2w = (const float*)d_in[5];
    const float* c2b = (const float*)d_in[6];
    const float* g2g = (const float*)d_in[7];
    const float* g2b = (const float*)d_in[8];
    const float* c3w = (const float*)d_in[9];
    const float* c3b = (const float*)d_in[10];
    const float* g3g = (const float*)d_in[11];
    const float* g3b = (const float*)d_in[12];
    const float* fcw = (const float*)d_in[13];
    const float* fcb = (const float*)d_in[14];
    const float* wq  = (const float*)d_in[15];
    const float* bq  = (const float*)d_in[16];
    const float* wk  = (const float*)d_in[17];
    const float* bk  = (const float*)d_in[18];
    const float* wv  = (const float*)d_in[19];
    const float* bv  = (const float*)d_in[20];
    float* out = (float*)d_out;

    cudaFuncSetAttribute(k_conv2mma, cudaFuncAttributeMaxDynamicSharedMemorySize, C2_SMEM);
    cudaFuncSetAttribute(k_conv3mma4, cudaFuncAttributeMaxDynamicSharedMemorySize, C3_SMEM);

    k_zero<<<1, 256>>>();
    k_prep<<<768, 256>>>(c2w, c3w);
    k_conv1<<<1024, 256>>>(x, c1w, c1b, g1g, g1b);
    k_conv2mma<<<dim3(1024,2), 384, C2_SMEM>>>(c2b, g2g, g2b);
    k_conv3mma4<<<256, 512, C3_SMEM>>>(c3b, g3g, g3b);
    k_fc  <<<128, 256>>>(fcw, fcb);
    k_qkv <<<128, 256>>>(wq, bq, wk, bk, wv, bv);
    k_attn<<<128, 256>>>();
    k_cs1 <<<64, 256>>>();
    k_cs2 <<<64, 256>>>();
    k_cs3r<<<1024, 128>>>();
    k_gram<<<dim3(32,32), 256>>>(out);
    k_final<<<4096, 256>>>(out);
}

// round 17
// speedup vs baseline: 1.2254x; 1.0541x over previous
#include <cuda_runtime.h>
#include <math.h>

#define NS 1024

__device__ float g_h1p[NS*32*36*16];
__device__ float g_h2p[NS*64*12*4];
__device__ float g_h3p[NS*128*4*2];
__device__ float g_w2p[2*4*24*2*32*4];
__device__ float g_w3p[16*12*8*32*4];
__device__ float g_e [NS*128];
__device__ float g_q [NS*128];
__device__ float g_k [NS*128];
__device__ float g_v [NS*128];
__device__ float g_ao[NS*128];
__device__ float g_o2[NS*128];
__device__ float g_ea[NS*128];
__device__ float g_sq[NS];
__device__ float g_css[128];
__device__ float g_css2[128];
__device__ unsigned int g_dmax;

__device__ __forceinline__ float selu_f(float x) {
    const float a = 1.6732632423543772f, sc = 1.0507009873554805f;
    return x > 0.f ? sc * x : sc * a * (expf(x) - 1.f);
}

__device__ __forceinline__ float2 ffma2(float2 a, float2 b, float2 c) {
    unsigned long long ua = *(unsigned long long*)&a;
    unsigned long long ub = *(unsigned long long*)&b;
    unsigned long long uc = *(unsigned long long*)&c;
    unsigned long long ud;
    asm("fma.rn.f32x2 %0, %1, %2, %3;" : "=l"(ud) : "l"(ua), "l"(ub), "l"(uc));
    return *(float2*)&ud;
}

__device__ __forceinline__ unsigned tf32c(float x) {
    unsigned u; asm("cvt.rna.tf32.f32 %0, %1;" : "=r"(u) : "f"(x)); return u;
}
__device__ __forceinline__ float tf32f(float x) {
    return __uint_as_float(tf32c(x));
}
__device__ __forceinline__ void mma_tf32(float* d, const unsigned* a, const unsigned* b) {
    asm volatile("mma.sync.aligned.m16n8k8.row.col.f32.tf32.tf32.f32 "
        "{%0,%1,%2,%3}, {%4,%5,%6,%7}, {%8,%9}, {%0,%1,%2,%3};"
        : "+f"(d[0]), "+f"(d[1]), "+f"(d[2]), "+f"(d[3])
        : "r"(a[0]), "r"(a[1]), "r"(a[2]), "r"(a[3]), "r"(b[0]), "r"(b[1]));
}

__device__ __forceinline__ unsigned s2u(const void* p) {
    return (unsigned)__cvta_generic_to_shared(p);
}
template<int IMM>
__device__ __forceinline__ unsigned lds1(unsigned a) {
    unsigned v;
    asm volatile("ld.shared.b32 %0, [%1+%2];" : "=r"(v) : "r"(a), "n"(IMM));
    return v;
}
template<int IMM>
__device__ __forceinline__ uint4 lds4(unsigned a) {
    uint4 v;
    asm volatile("ld.shared.v4.b32 {%0,%1,%2,%3}, [%4+%5];"
                 : "=r"(v.x), "=r"(v.y), "=r"(v.z), "=r"(v.w) : "r"(a), "n"(IMM));
    return v;
}
__device__ __forceinline__ void cpa4(void* dst, const void* src, int sz) {
    asm volatile("cp.async.ca.shared.global [%0], [%1], 4, %2;"
                 :: "r"(s2u(dst)), "l"(src), "r"(sz));
}
__device__ __forceinline__ void cpa16(void* dst, const void* src) {
    asm volatile("cp.async.cg.shared.global [%0], [%1], 16;"
                 :: "r"(s2u(dst)), "l"(src));
}
__device__ __forceinline__ void cpa_commit() { asm volatile("cp.async.commit_group;"); }
template<int N> __device__ __forceinline__ void cpa_wait() {
    asm volatile("cp.async.wait_group %0;" :: "n"(N));
}

__global__ void k_zero() {
    int t = threadIdx.x;
    if (t < 128) { g_css[t] = 0.f; g_css2[t] = 0.f; }
    if (t == 255) g_dmax = 0u;
}

// pre-convert + pack weights so each thread's A fragment is one float4
__global__ void __launch_bounds__(256) k_prep(const float* __restrict__ w2,
        const float* __restrict__ w3) {
    int i = blockIdx.x*256 + threadIdx.x;
    if (i < 49152) {
        int q = i & 3, t = (i>>2) & 31, m = (i>>7) & 1;
        int sl = (i>>8) % 24, rest = (i>>8) / 24;
        int ck = rest & 3, ob = rest >> 2;
        int k_loc = (sl/3)*24 + (sl%3)*8 + (t&3) + ((q>>1)<<2);
        int oc = ob*32 + m*16 + (t>>2) + ((q&1)<<3);
        g_w2p[i] = tf32f(w2[oc*768 + ck*192 + k_loc]);
    }
    if (i < 196608) {
        int q = i & 3, t = (i>>2) & 31, m = (i>>7) & 7;
        int sl = (i>>10) % 12, ck = (i>>10) / 12;
        int k_loc = (sl/3)*24 + (sl%3)*8 + (t&3) + ((q>>1)<<2);
        int oc = m*16 + (t>>2) + ((q&1)<<3);
        g_w3p[i] = tf32f(w3[oc*1536 + ck*96 + k_loc]);
    }
}

// ===== conv1 =====
__global__ void __launch_bounds__(256) k_conv1(const float* __restrict__ x,
        const float* __restrict__ w, const float* __restrict__ bias,
        const float* __restrict__ gg, const float* __restrict__ gb) {
    __shared__ __align__(16) float pad[77*68];
    int s = blockIdx.x, tid = threadIdx.x, lane = tid & 31;
    const float* xs = x + s*4608;
    for (int i = tid; i < 77*68; i += 256) {
        int r = i/68, cc = i - r*68;
        int ih = r-2, iw = cc-1;
        pad[i] = (ih>=0 && ih<72 && iw>=0 && iw<64) ? xs[ih*64+iw] : 0.f;
    }
    __syncthreads();
    for (int cc4 = 0; cc4 < 4; cc4++) {
        int ch = cc4*8 + (tid>>5);
        float2 w2[24];
        #pragma unroll
        for (int k2 = 0; k2 < 24; k2++) { float wv = w[ch*24+k2]; w2[k2] = make_float2(wv, wv); }
        float bi = bias[ch];
        float pm[18], pn[18], sum = 0.f, sq = 0.f;
        for (int wi = 0; wi < 18; wi++) {
            int wdw = wi*32 + lane;
            int ph = wdw>>4, pw = wdw&15;
            float2 acc[2][2];
            #pragma unroll
            for (int r = 0; r < 2; r++)
                #pragma unroll
                for (int cp = 0; cp < 2; cp++) acc[r][cp] = make_float2(bi, bi);
            #pragma unroll
            for (int ir = 0; ir < 7; ir++) {
                const float* pr = &pad[(2*ph+ir)*68 + 4*pw];
                float4 va = *(const float4*)pr;
                float4 vb = *(const float4*)(pr + 4);
                float v[7] = {va.x, va.y, va.z, va.w, vb.x, vb.y, vb.z};
                #pragma unroll
                for (int r = 0; r < 2; r++) {
                    int kh = ir - r;
                    if (kh >= 0 && kh < 6) {
                        #pragma unroll
                        for (int kw = 0; kw < 4; kw++) {
                            float2 wv = w2[kh*4+kw];
                            #pragma unroll
                            for (int cp = 0; cp < 2; cp++)
                                acc[r][cp] = ffma2(make_float2(v[2*cp+kw], v[2*cp+kw+1]), wv, acc[r][cp]);
                        }
                    }
                }
            }
            float mx = -1e30f, mn = 1e30f;
            #pragma unroll
            for (int r = 0; r < 2; r++)
                #pragma unroll
                for (int cp = 0; cp < 2; cp++) {
                    float u0 = selu_f(acc[r][cp].x), u1 = selu_f(acc[r][cp].y);
                    sum += u0+u1; sq += u0*u0+u1*u1;
                    mx = fmaxf(mx, fmaxf(u0,u1)); mn = fminf(mn, fminf(u0,u1));
                }
            pm[wi] = mx; pn[wi] = mn;
        }
        #pragma unroll
        for (int o = 16; o; o >>= 1) {
            sum += __shfl_xor_sync(0xffffffffu, sum, o);
            sq  += __shfl_xor_sync(0xffffffffu, sq , o);
        }
        float mean = sum*(1.f/4608.f);
        float var  = sq*(1.f/4608.f) - mean*mean;
        float sc = gg[ch]*rsqrtf(var+1e-5f);
        float sh = gb[ch] - mean*sc;
        for (int wi = 0; wi < 18; wi++) {
            int wdw = wi*32 + lane;
            int ph = wdw>>4, pw = wdw&15;
            float val = sc>0.f ? pm[wi]*sc+sh : pn[wi]*sc+sh;
            g_h1p[((s*32+ch)*36+ph)*16+pw] = tf32f(val);
        }
    }
}

// ===== conv2: TF32 mma, float4 A fragments, cp.async double-buffered =====
#define C2_STG 12376
#define C2_SMEM (2*C2_STG*4)
#define C2_STEP(U) { \
    uint4 Av = lds4<(U)*1024>(wp); \
    unsigned A[4] = {Av.x, Av.y, Av.z, Av.w}; \
    _Pragma("unroll") \
    for (int j = 0; j < 12; j++) { \
        unsigned B[2]; \
        B[0] = lds1<(38*(U))*4>(bp[j]); \
        B[1] = lds1<(38*(U)+19)*4>(bp[j]); \
        mma_tf32(cfr[j], A, B); \
    } }
__global__ void __launch_bounds__(384, 2) k_conv2mma(const float* __restrict__ bias,
        const float* __restrict__ gg, const float* __restrict__ gb) {
    extern __shared__ float dsm[];
    float* cv = dsm;
    int s = blockIdx.x, ob = blockIdx.y, ocb = 32*ob;
    int tid = threadIdx.x, wrp = tid>>5, t = tid&31;
    int m = wrp & 1, ng = wrp >> 1;
    float cfr[12][4];
    #pragma unroll
    for (int j = 0; j < 12; j++) { cfr[j][0]=cfr[j][1]=cfr[j][2]=cfr[j][3]=0.f; }
    int off[12];
    #pragma unroll
    for (int j = 0; j < 12; j++) {
        int n = ng*96 + j*8 + (t>>2);
        off[j] = (n>>4)*19 + (n&15);
    }
    auto stage = [&](int ck, float* buf) {
        float* wsb = buf;
        float* padb = buf + 6144;
        #pragma unroll
        for (int u = 0; u < 4; u++) {
            int i4 = (tid + u*384)*4;
            cpa16(&wsb[i4], &g_w2p[ob*24576 + ck*6144 + i4]);
        }
        for (int i = tid; i < 6232; i += 384) {
            int icl = i/779, rem = i - icl*779;
            int row = rem/19, col = rem - row*19;
            int ih = row - 2, iw = col - 1;
            bool ok = (ih>=0 && ih<36 && iw>=0 && iw<16);
            cpa4(&padb[i],
                 &g_h1p[((s*32 + ck*8 + icl)*36 + (ok?ih:0))*16 + (ok?iw:0)],
                 ok ? 4 : 0);
        }
        cpa_commit();
    };
    stage(0, dsm);
    for (int ck = 0; ck < 4; ck++) {
        if (ck > 0) __syncthreads();
        if (ck < 3) stage(ck+1, dsm + ((ck+1)&1)*C2_STG);
        if (ck < 3) cpa_wait<1>(); else cpa_wait<0>();
        __syncthreads();
        unsigned wsb = s2u(dsm + (ck&1)*C2_STG);
        unsigned wp = wsb + (m*32 + t)*16;
        unsigned bp[12];
        #pragma unroll
        for (int j = 0; j < 12; j++) bp[j] = wsb + 6144*4 + ((t&3) + off[j])*4;
        #pragma unroll 1
        for (int icl = 0; icl < 8; icl++) {
            C2_STEP(0)
            C2_STEP(1)
            C2_STEP(2)
            wp += 3072;
            #pragma unroll
            for (int j = 0; j < 12; j++) bp[j] += 779*4;
        }
    }
    __syncthreads();
    int ocl = m*16 + (t>>2);
    float b0v = bias[ocb+ocl], b8v = bias[ocb+ocl+8];
    #pragma unroll
    for (int j = 0; j < 12; j++) {
        int n0 = ng*96 + j*8 + (t&3)*2;
        cv[ocl*577 + n0]     = selu_f(cfr[j][0] + b0v);
        cv[ocl*577 + n0 + 1] = selu_f(cfr[j][1] + b0v);
        cv[(ocl+8)*577 + n0]     = selu_f(cfr[j][2] + b8v);
        cv[(ocl+8)*577 + n0 + 1] = selu_f(cfr[j][3] + b8v);
    }
    __syncthreads();
    if (tid < 256) {
        int g = tid>>4, e = tid&15;
        float sm = 0.f, sq = 0.f;
        #pragma unroll
        for (int cl = 0; cl < 2; cl++)
            for (int i = e; i < 576; i += 16) {
                float v = cv[(2*g+cl)*577 + i];
                sm += v; sq += v*v;
            }
        #pragma unroll
        for (int o = 8; o; o >>= 1) {
            sm += __shfl_xor_sync(0xffffffffu, sm, o);
            sq += __shfl_xor_sync(0xffffffffu, sq, o);
        }
        float mean = sm*(1.f/1152.f);
        float var  = sq*(1.f/1152.f) - mean*mean;
        float inv  = rsqrtf(var + 1e-5f);
        #pragma unroll
        for (int ii = 0; ii < 6; ii++) {
            int u = e + 16*ii;
            int cl = u/48, rem = u - cl*48;
            int ph = rem>>2, pw = rem&3;
            float scv = gg[ocb+2*g+cl]*inv;
            float shv = gb[ocb+2*g+cl] - mean*scv;
            float mx = -1e30f;
            #pragma unroll
            for (int r = 0; r < 3; r++)
                #pragma unroll
                for (int c = 0; c < 4; c++)
                    mx = fmaxf(mx, cv[(2*g+cl)*577 + (3*ph+r)*16 + 4*pw+c]*scv + shv);
            g_h2p[((s*64 + ocb + 2*g + cl)*12 + ph)*4 + pw] = tf32f(mx);
        }
    }
}

// ===== conv3: TF32 mma, 4 frames/block, float4 A, cp.async double-buffered =====
#define C3_STG 14192
#define C3_SMEM (2*C3_STG*4)
#define C3_STEP(U) { \
    uint4 Av = lds4<(U)*4096>(wp); \
    unsigned A[4] = {Av.x, Av.y, Av.z, Av.w}; \
    _Pragma("unroll") \
    for (int j = 0; j < 12; j++) { \
        unsigned B[2]; \
        B[0] = lds1<(14*(U))*4>(bp[j]); \
        B[1] = lds1<(14*(U)+7)*4>(bp[j]); \
        mma_tf32(cfr[j], A, B); \
    } }
__global__ void __launch_bounds__(512) k_conv3mma4(const float* __restrict__ bias,
        const float* __restrict__ gg, const float* __restrict__ gb) {
    extern __shared__ float dsm3[];
    float* cv = dsm3;
    int s4 = blockIdx.x*4, tid = threadIdx.x, wrp = tid>>5, t = tid&31;
    int m = wrp & 7, ng = wrp >> 3;
    float cfr[12][4];
    #pragma unroll
    for (int j = 0; j < 12; j++) { cfr[j][0]=cfr[j][1]=cfr[j][2]=cfr[j][3]=0.f; }
    int off[12];
    #pragma unroll
    for (int j = 0; j < 12; j++) {
        int n = ng*96 + j*8 + (t>>2);
        int f = (ng*96 + j*8)/48;
        int np = n - 48*f;
        off[j] = f*476 + (np>>2)*7 + (np&3);
    }
    auto stage = [&](int ck, float* buf) {
        float* wsb = buf;
        float* padb = buf + 12288;
        #pragma unroll
        for (int u = 0; u < 6; u++) {
            int i4 = (tid + u*512)*4;
            cpa16(&wsb[i4], &g_w3p[ck*12288 + i4]);
        }
        for (int i = tid; i < 1904; i += 512) {
            int f = i/476, rem = i - f*476;
            int icl = rem/119, rem2 = rem - icl*119;
            int rr = rem2/7, cc = rem2 - rr*7;
            int ih = rr-2, iw = cc-1;
            bool ok = (ih>=0 && ih<12 && iw>=0 && iw<4);
            cpa4(&padb[i],
                 &g_h2p[(((s4+f)*64 + ck*4 + icl)*12 + (ok?ih:0))*4 + (ok?iw:0)],
                 ok ? 4 : 0);
        }
        cpa_commit();
    };
    stage(0, dsm3);
    for (int ck = 0; ck < 16; ck++) {
        if (ck > 0) __syncthreads();
        if (ck < 15) stage(ck+1, dsm3 + ((ck+1)&1)*C3_STG);
        if (ck < 15) cpa_wait<1>(); else cpa_wait<0>();
        __syncthreads();
        unsigned wsb = s2u(dsm3 + (ck&1)*C3_STG);
        unsigned wp = wsb + (m*32 + t)*16;
        unsigned bp[12];
        #pragma unroll
        for (int j = 0; j < 12; j++) bp[j] = wsb + 12288*4 + ((t&3) + off[j])*4;
        #pragma unroll 1
        for (int icl = 0; icl < 4; icl++) {
            C3_STEP(0)
            C3_STEP(1)
            C3_STEP(2)
            wp += 12288;
            #pragma unroll
            for (int j = 0; j < 12; j++) bp[j] += 119*4;
        }
    }
    int oc0 = m*16 + (t>>2);
    float b0v = bias[oc0], b8v = bias[oc0+8];
    for (int f = 0; f < 4; f++) {
        __syncthreads();
        #pragma unroll
        for (int j = 0; j < 12; j++) {
            int fj = ng*2 + j/6;
            if (fj == f) {
                int np = (j - (j/6)*6)*8 + (t&3)*2;
                cv[oc0*49 + np]     = selu_f(cfr[j][0] + b0v);
                cv[oc0*49 + np + 1] = selu_f(cfr[j][1] + b0v);
                cv[(oc0+8)*49 + np]     = selu_f(cfr[j][2] + b8v);
                cv[(oc0+8)*49 + np + 1] = selu_f(cfr[j][3] + b8v);
            }
        }
        __syncthreads();
        int g = tid>>4, e = tid&15;
        float sm = 0.f, sq = 0.f;
        #pragma unroll
        for (int cl = 0; cl < 4; cl++)
            for (int i = e; i < 48; i += 16) {
                float v = cv[(4*g+cl)*49 + i];
                sm += v; sq += v*v;
            }
        #pragma unroll
        for (int o = 8; o; o >>= 1) {
            sm += __shfl_xor_sync(0xffffffffu, sm, o);
            sq += __shfl_xor_sync(0xffffffffu, sq, o);
        }
        float mean = sm*(1.f/192.f);
        float var  = sq*(1.f/192.f) - mean*mean;
        float inv  = rsqrtf(var + 1e-5f);
        #pragma unroll
        for (int ii = 0; ii < 2; ii++) {
            int u = e + 16*ii;
            int cl = u>>3, rem = u&7;
            int ph = rem>>1, pw = rem&1;
            float scv = gg[4*g+cl]*inv;
            float shv = gb[4*g+cl] - mean*scv;
            float mx = -1e30f;
            #pragma unroll
            for (int r = 0; r < 3; r++)
                #pragma unroll
                for (int c = 0; c < 2; c++)
                    mx = fmaxf(mx, cv[(4*g+cl)*49 + (3*ph+r)*4 + 2*pw+c]*scv + shv);
            g_h3p[(((s4+f)*128 + 4*g + cl)*4 + ph)*2 + pw] = mx;
        }
    }
}

// ===== fc =====
__global__ void __launch_bounds__(256) k_fc(const float* __restrict__ w,
        const float* __restrict__ bias) {
    __shared__ float xs[8*65];
    __shared__ float wt[64*129];
    __shared__ float sred[8][4];
    int r0 = blockIdx.x*8, tid = threadIdx.x;
    int c = tid&127, rg = tid>>7, wrp = tid>>5, ln = tid&31;
    float acc[4];
    float b0 = bias[c];
    #pragma unroll
    for (int rr = 0; rr < 4; rr++) acc[rr] = b0;
    for (int k0 = 0; k0 < 1024; k0 += 64) {
        __syncthreads();
        for (int i = tid; i < 512; i += 256) {
            int r = i>>6, kk = i&63;
            xs[r*65+kk] = g_h3p[(r0+r)*1024 + k0 + kk];
        }
        for (int i = tid; i < 8192; i += 256) {
            int j = i>>6, kk = i&63;
            wt[kk*129+j] = w[j*1024 + k0 + kk];
        }
        __syncthreads();
        for (int kk = 0; kk < 64; kk++) {
            float wv = wt[kk*129+c];
            #pragma unroll
            for (int rr = 0; rr < 4; rr++) acc[rr] += xs[(rg*4+rr)*65+kk]*wv;
        }
    }
    float v[4];
    #pragma unroll
    for (int rr = 0; rr < 4; rr++) v[rr] = selu_f(acc[rr]);
    #pragma unroll
    for (int rr = 0; rr < 4; rr++) {
        float ss = v[rr]*v[rr];
        #pragma unroll
        for (int o = 16; o; o >>= 1) ss += __shfl_xor_sync(0xffffffffu, ss, o);
        if (ln == 0) sred[wrp][rr] = ss;
    }
    __syncthreads();
    #pragma unroll
    for (int rr = 0; rr < 4; rr++) {
        float t = sred[rg*4+0][rr] + sred[rg*4+1][rr] + sred[rg*4+2][rr] + sred[rg*4+3][rr];
        float n = fmaxf(sqrtf(t), 1e-12f);
        g_e[(r0+rg*4+rr)*128 + c] = v[rr]/n;
    }
}

// ===== qkv =====
__global__ void __launch_bounds__(256) k_qkv(const float* __restrict__ wq,
        const float* __restrict__ bq, const float* __restrict__ wk,
        const float* __restrict__ bk, const float* __restrict__ wv,
        const float* __restrict__ bv) {
    __shared__ float es[8*132];
    __shared__ float wt[64*129];
    int r0 = blockIdx.x*8, tid = threadIdx.x;
    int c = tid&127, rg = tid>>7;
    for (int i = tid; i < 1024; i += 256) {
        int r = i>>7, d = i&127;
        es[r*132+d] = g_e[(r0+r)*128 + d];
    }
    const float* W[3] = {wq, wk, wv};
    const float* B[3] = {bq, bk, bv};
    float* O[3] = {g_q, g_k, g_v};
    for (int m = 0; m < 3; m++) {
        float acc[4];
        float b0 = B[m][c];
        #pragma unroll
        for (int rr = 0; rr < 4; rr++) acc[rr] = b0;
        for (int k0 = 0; k0 < 128; k0 += 64) {
            __syncthreads();
            for (int i = tid; i < 8192; i += 256) {
                int j = i>>6, kk = i&63;
                wt[kk*129+j] = W[m][j*128 + k0 + kk];
            }
            __syncthreads();
            for (int kk = 0; kk < 64; kk++) {
                float wvv = wt[kk*129+c];
                #pragma unroll
                for (int rr = 0; rr < 4; rr++) acc[rr] += es[(rg*4+rr)*132 + k0 + kk]*wvv;
            }
        }
        #pragma unroll
        for (int rr = 0; rr < 4; rr++) {
            int sr = r0 + rg*4 + rr;
            float u = selu_f(acc[rr]);
            if (m == 1) {
                float f = expf((float)(c & ~1) * (-9.210340371976184f/128.f));
                float ang = (float)sr * f;
                u += (c & 1) ? cosf(ang) : sinf(ang);
            }
            O[m][sr*128 + c] = u;
        }
    }
}

// ===== attn =====
__global__ void __launch_bounds__(256) k_attn() {
    __shared__ __align__(16) float q8[8*132];
    __shared__ __align__(16) float p[8*1024];
    __shared__ float rinv[8];
    int r0 = blockIdx.x*8, tid = threadIdx.x;
    for (int i = tid; i < 1024; i += 256) {
        int r = i>>7, d = i&127;
        q8[r*132+d] = g_q[(r0+r)*128 + d];
    }
    __syncthreads();
    const float scale = 0.08838834764831845f;
    for (int t = tid; t < 1024; t += 256) {
        float2 a2[8];
        #pragma unroll
        for (int r = 0; r < 8; r++) a2[r] = make_float2(0.f, 0.f);
        const float4* kr = (const float4*)(g_k + t*128);
        #pragma unroll 4
        for (int d4 = 0; d4 < 32; d4++) {
            float4 kv = kr[d4];
            float2 klo = make_float2(kv.x, kv.y), khi = make_float2(kv.z, kv.w);
            #pragma unroll
            for (int r = 0; r < 8; r++) {
                float4 qv = *(const float4*)&q8[r*132 + d4*4];
                a2[r] = ffma2(make_float2(qv.x, qv.y), klo, a2[r]);
                a2[r] = ffma2(make_float2(qv.z, qv.w), khi, a2[r]);
            }
        }
        #pragma unroll
        for (int r = 0; r < 8; r++) p[r*1024+t] = (a2[r].x + a2[r].y)*scale;
    }
    __syncthreads();
    int wrp = tid>>5, ln = tid&31;
    {
        int r = wrp;
        float mxv = -1e30f;
        for (int t = ln; t < 1024; t += 32) mxv = fmaxf(mxv, p[r*1024+t]);
        #pragma unroll
        for (int o = 16; o; o >>= 1) mxv = fmaxf(mxv, __shfl_xor_sync(0xffffffffu, mxv, o));
        float sm = 0.f;
        for (int t = ln; t < 1024; t += 32) {
            float e = expf(p[r*1024+t] - mxv);
            p[r*1024+t] = e;
            sm += e;
        }
        #pragma unroll
        for (int o = 16; o; o >>= 1) sm += __shfl_xor_sync(0xffffffffu, sm, o);
        if (ln == 0) rinv[r] = 1.f/sm;
    }
    __syncthreads();
    int c2 = tid&63, hf = tid>>6;
    float2 acc2[8];
    #pragma unroll
    for (int r = 0; r < 8; r++) acc2[r] = make_float2(0.f, 0.f);
    for (int t = hf*256; t < hf*256+256; t++) {
        float2 vv = *(const float2*)&g_v[t*128 + 2*c2];
        #pragma unroll
        for (int r = 0; r < 8; r++) {
            float pv = p[r*1024+t];
            acc2[r] = ffma2(make_float2(pv, pv), vv, acc2[r]);
        }
    }
    __syncthreads();
    float2* pbuf = (float2*)p;
    if (hf) {
        #pragma unroll
        for (int r = 0; r < 8; r++) pbuf[(hf-1)*512 + r*64 + c2] = acc2[r];
    }
    __syncthreads();
    if (hf == 0) {
        #pragma unroll
        for (int r = 0; r < 8; r++) {
            float2 sv = acc2[r];
            #pragma unroll
            for (int q = 0; q < 3; q++) {
                float2 o = pbuf[q*512 + r*64 + c2];
                sv.x += o.x; sv.y += o.y;
            }
            g_ao[(r0+r)*128 + 2*c2]     = sv.x*rinv[r];
            g_ao[(r0+r)*128 + 2*c2 + 1] = sv.y*rinv[r];
        }
    }
}

__global__ void __launch_bounds__(256) k_cs1() {
    __shared__ float red[128];
    int s0 = blockIdx.x*16, tid = threadIdx.x;
    int c = tid&127, sy = tid>>7;
    float ss = 0.f;
    for (int s = sy; s < 16; s += 2) { float v = g_ao[(s0+s)*128+c]; ss += v*v; }
    if (sy) red[c] = ss;
    __syncthreads();
    if (!sy) atomicAdd(&g_css[c], ss + red[c]);
}

__global__ void __launch_bounds__(256) k_cs2() {
    __shared__ float red[128];
    int s0 = blockIdx.x*16, tid = threadIdx.x;
    int c = tid&127, sy = tid>>7;
    float inv1 = 1.f/fmaxf(sqrtf(g_css[c]), 1e-12f);
    float ss = 0.f;
    for (int s = sy; s < 16; s += 2) {
        float v = g_ao[(s0+s)*128+c]*inv1 + g_e[(s0+s)*128+c];
        g_o2[(s0+s)*128+c] = v;
        ss += v*v;
    }
    if (sy) red[c] = ss;
    __syncthreads();
    if (!sy) atomicAdd(&g_css2[c], ss + red[c]);
}

__global__ void __launch_bounds__(128) k_cs3r() {
    __shared__ float red[4];
    int s = blockIdx.x, d = threadIdx.x;
    int wrp = d>>5, ln = d&31;
    float inv2 = 1.f/fmaxf(sqrtf(g_css2[d]), 1e-12f);
    float v = g_o2[s*128+d]*inv2;
    g_ea[s*128+d] = v;
    float ss = v*v;
    #pragma unroll
    for (int o = 16; o; o >>= 1) ss += __shfl_xor_sync(0xffffffffu, ss, o);
    if (ln == 0) red[wrp] = ss;
    __syncthreads();
    if (d == 0) g_sq[s] = red[0]+red[1]+red[2]+red[3];
}

__global__ void k_gram(float* __restrict__ dout) {
    __shared__ float ea_i[32][129];
    __shared__ float ea_j[32][129];
    __shared__ float sqi[32], sqj[32];
    __shared__ float rmax[8];
    int i0 = blockIdx.y*32, j0 = blockIdx.x*32;
    int tid = threadIdx.x;
    for (int idx = tid; idx < 4096; idx += 256) {
        int r = idx>>7, d = idx&127;
        ea_i[r][d] = g_ea[(i0+r)*128+d];
        ea_j[r][d] = g_ea[(j0+r)*128+d];
    }
    if (tid < 32) { sqi[tid] = g_sq[i0+tid]; sqj[tid] = g_sq[j0+tid]; }
    __syncthreads();
    int tx = tid&15, ty = tid>>4;
    int r0 = 2*ty, c0 = 2*tx;
    float d00 = 0.f, d01 = 0.f, d10 = 0.f, d11 = 0.f;
    #pragma unroll 4
    for (int d = 0; d < 128; d++) {
        float a0 = ea_i[r0][d], a1 = ea_i[r0+1][d];
        float b0 = ea_j[c0][d], b1 = ea_j[c0+1][d];
        d00 += a0*b0; d01 += a0*b1; d10 += a1*b0; d11 += a1*b1;
    }
    float lm = 0.f;
    float dots[4] = {d00, d01, d10, d11};
    #pragma unroll
    for (int u = 0; u < 4; u++) {
        int r = r0 + (u>>1), c = c0 + (u&1);
        float d2 = fmaxf(sqi[r] + sqj[c] - 2.f*dots[u], 0.f);
        float dd = sqrtf(d2 + 1e-12f);
        dout[(i0+r)*1024 + j0 + c] = dd;
        lm = fmaxf(lm, dd);
    }
    #pragma unroll
    for (int o = 16; o; o >>= 1) lm = fmaxf(lm, __shfl_xor_sync(0xffffffffu, lm, o));
    if ((tid&31) == 0) rmax[tid>>5] = lm;
    __syncthreads();
    if (tid == 0) {
        float m = 0.f;
        for (int i = 0; i < 8; i++) m = fmaxf(m, rmax[i]);
        atomicMax(&g_dmax, __float_as_uint(m));
    }
}

__global__ void k_final(float* __restrict__ dout) {
    float inv = 1.f/__uint_as_float(g_dmax);
    int i = blockIdx.x*256 + threadIdx.x;
    dout[i] = 1.f - dout[i]*inv;
}

extern "C" void kernel_launch(void* const* d_in, const int* in_sizes, int n_in,
                              void* d_out, int out_size) {
    const float* x   = (const float*)d_in[0];
    const float* c1w = (const float*)d_in[1];
    const float* c1b = (const float*)d_in[2];
    const float* g1g = (const float*)d_in[3];
    const float* g1b = (const float*)d_in[4];
    const float* c2w = (const float*)d_in[5];
    const float* c2b = (const float*)d_in[6];
    const float* g2g = (const float*)d_in[7];
    const float* g2b = (const float*)d_in[8];
    const float* c3w = (const float*)d_in[9];
    const float* c3b = (const float*)d_in[10];
    const float* g3g = (const float*)d_in[11];
    const float* g3b = (const float*)d_in[12];
    const float* fcw = (const float*)d_in[13];
    const float* fcb = (const float*)d_in[14];
    const float* wq  = (const float*)d_in[15];
    const float* bq  = (const float*)d_in[16];
    const float* wk  = (const float*)d_in[17];
    const float* bk  = (const float*)d_in[18];
    const float* wv  = (const float*)d_in[19];
    const float* bv  = (const float*)d_in[20];
    float* out = (float*)d_out;

    cudaFuncSetAttribute(k_conv2mma, cudaFuncAttributeMaxDynamicSharedMemorySize, C2_SMEM);
    cudaFuncSetAttribute(k_conv3mma4, cudaFuncAttributeMaxDynamicSharedMemorySize, C3_SMEM);

    k_zero<<<1, 256>>>();
    k_prep<<<768, 256>>>(c2w, c3w);
    k_conv1<<<1024, 256>>>(x, c1w, c1b, g1g, g1b);
    k_conv2mma<<<dim3(1024,2), 384, C2_SMEM>>>(c2b, g2g, g2b);
    k_conv3mma4<<<256, 512, C3_SMEM>>>(c3b, g3g, g3b);
    k_fc  <<<128, 256>>>(fcw, fcb);
    k_qkv <<<128, 256>>>(wq, bq, wk, bk, wv, bv);
    k_attn<<<128, 256>>>();
    k_cs1 <<<64, 256>>>();
    k_cs2 <<<64, 256>>>();
    k_cs3r<<<1024, 128>>>();
    k_gram<<<dim3(32,32), 256>>>(out);
    k_final<<<4096, 256>>>(out);
}